// round 5
// baseline (speedup 1.0000x reference)
#include <cuda_runtime.h>
#include <math.h>
#include <stdint.h>

#define BB   8
#define DD   1024
#define NPTS 4096
#define KK   64
#define HH   512

#define SEPS 1e-3f
#define INV_EPS (1.0f/1e-3f)

// ---------------- scratch (device globals; no allocation) ----------------
static __device__ float g_y1[BB*HH*NPTS];      // 64MB
static __device__ float g_y2[BB*HH*NPTS];      // 64MB
static __device__ float g_ls[BB*KK*NPTS];      // 8MB  log_score
static __device__ float g_score[BB*KK*NPTS];   // 8MB
static __device__ float g_lsn[BB*NPTS];
static __device__ float g_pi[BB*KK];
static __device__ float g_sc1[HH], g_sh1[HH], g_sc2[HH], g_sh2[HH];
static __device__ float g_muxyz[BB*3*KK];
static __device__ float g_mufea[BB*DD*KK];
static __device__ float g_invf[BB*NPTS];
static __device__ float g_invmu[BB*KK];
static __device__ float g_costx[BB*NPTS*KK];
static __device__ float g_costxT[BB*KK*NPTS];
static __device__ float g_costf[BB*NPTS*KK];
static __device__ float g_costfT[BB*KK*NPTS];
static __device__ float g_u[2*BB*NPTS];
static __device__ float g_v[2*BB*KK];
static __device__ float g_acc[4];

// ================= 3xTF32 GEMM via mma.sync (baseline PTX, sm_80+) =================
// C[b][m][n] = sum_k W[m][k] * X[b][k][n] + bias[m]
// CTA tile 128Mx128N, BK=32. 8 warps: wm=wid/4 (2), wn=wid%4 (4); warp tile 64x32.
// SMEM stored in fragment order: per buffer Ah[0:4096) Al[4096:8192) Bh[8192:12288)
// Bl[12288:16384) words; two buffers; total 128 KB.

__device__ __forceinline__ void tf32_split(float x, uint32_t& h, uint32_t& l) {
    uint32_t hh;
    asm("cvt.rna.tf32.f32 %0, %1;" : "=r"(hh) : "f"(x));
    float lo = x - __uint_as_float(hh);
    uint32_t ll;
    asm("cvt.rna.tf32.f32 %0, %1;" : "=r"(ll) : "f"(lo));
    h = hh; l = ll;
}

#define MMA8(d, a, b) \
    asm volatile("mma.sync.aligned.m16n8k8.row.col.f32.tf32.tf32.f32 " \
        "{%0,%1,%2,%3}, {%4,%5,%6,%7}, {%8,%9}, {%0,%1,%2,%3};" \
        : "+f"((d)[0]), "+f"((d)[1]), "+f"((d)[2]), "+f"((d)[3]) \
        : "r"((a).x), "r"((a).y), "r"((a).z), "r"((a).w), "r"((b).x), "r"((b).y))

// fragment-order offsets (in 32-bit words), each array 4096 words (16KB)
__device__ __forceinline__ int a_off(int m, int kk) {
    return (((m >> 4) * 4 + (kk >> 3)) << 7) + (((m & 7) * 4 + (kk & 3)) << 2)
         + ((m >> 3) & 1) + (((kk >> 2) & 1) << 1);
}
__device__ __forceinline__ int b_off(int kk, int n) {
    return (((n >> 3) * 4 + (kk >> 3)) << 6) + (((n & 7) * 4 + (kk & 3)) << 1)
         + ((kk >> 2) & 1);
}

#define GEMM_SMEM (2 * 16384 * sizeof(float))   // 128 KB

__global__ __launch_bounds__(256, 1)
void mma_gemm_kernel(const float* __restrict__ W, const float* __restrict__ X,
                     const float* __restrict__ bias, float* __restrict__ C,
                     int Kd, int Mtot)
{
    extern __shared__ uint32_t sm[];
    const int tid = threadIdx.x, wid = tid >> 5, lane = tid & 31;
    const int wm = wid >> 2, wn = wid & 3;
    const int b = blockIdx.z, n0 = blockIdx.x * 128, m0 = blockIdx.y * 128;
    const float* Xb = X + (size_t)b * Kd * NPTS;
    float* Cb = C + (size_t)b * Mtot * NPTS;

    float acc[4][4][4];
#pragma unroll
    for (int i = 0; i < 4; i++)
#pragma unroll
        for (int j = 0; j < 4; j++)
#pragma unroll
            for (int r = 0; r < 4; r++) acc[i][j][r] = 0.0f;

    const int CH = Kd / 32;
    float4 areg[4], breg[4];

    auto load_regs = [&](int k0) {
#pragma unroll
        for (int i = 0; i < 4; i++) {
            int t4 = tid + i * 256;            // A: 128 rows x 8 quads
            int m = t4 >> 3, kq = t4 & 7;
            int msrc = m0 + m;
            if (msrc >= Mtot) msrc -= Mtot;    // row-dup for Mtot=64 (GEMM3)
            areg[i] = *reinterpret_cast<const float4*>(W + (size_t)msrc * Kd + k0 + kq * 4);
        }
#pragma unroll
        for (int i = 0; i < 4; i++) {
            int t4 = tid + i * 256;            // B: 32 k x 32 quads of n
            int kk = t4 >> 5, nq = t4 & 31;
            breg[i] = *reinterpret_cast<const float4*>(Xb + (size_t)(k0 + kk) * NPTS + n0 + nq * 4);
        }
    };

    auto store_smem = [&](int buf) {
        uint32_t* Ah = sm + buf * 16384;
        uint32_t* Al = Ah + 4096;
        uint32_t* Bh = Ah + 8192;
        uint32_t* Bl = Ah + 12288;
#pragma unroll
        for (int i = 0; i < 4; i++) {
            int t4 = tid + i * 256;
            int m = t4 >> 3, kq = t4 & 7;
            const float* v = reinterpret_cast<const float*>(&areg[i]);
#pragma unroll
            for (int j = 0; j < 4; j++) {
                uint32_t h, l;
                tf32_split(v[j], h, l);
                int o = a_off(m, kq * 4 + j);
                Ah[o] = h; Al[o] = l;
            }
        }
#pragma unroll
        for (int i = 0; i < 4; i++) {
            int t4 = tid + i * 256;
            int kk = t4 >> 5, nq = t4 & 31;
            const float* v = reinterpret_cast<const float*>(&breg[i]);
#pragma unroll
            for (int j = 0; j < 4; j++) {
                uint32_t h, l;
                tf32_split(v[j], h, l);
                int o = b_off(kk, nq * 4 + j);
                Bh[o] = h; Bl[o] = l;
            }
        }
    };

    load_regs(0);
    store_smem(0);
    __syncthreads();

    for (int c = 0; c < CH; c++) {
        int p = c & 1;
        if (c + 1 < CH) load_regs((c + 1) * 32);

        const uint32_t* Ah = sm + p * 16384;
        const uint32_t* Al = Ah + 4096;
        const uint32_t* Bh = Ah + 8192;
        const uint32_t* Bl = Ah + 12288;

#pragma unroll
        for (int ks = 0; ks < 4; ks++) {
            uint4 ah[4], al[4];
            uint2 bh[4], bl[4];
#pragma unroll
            for (int mt = 0; mt < 4; mt++) {
                int mtg = wm * 4 + mt;
                int o = ((mtg * 4 + ks) * 32 + lane) * 4;
                ah[mt] = *reinterpret_cast<const uint4*>(Ah + o);
                al[mt] = *reinterpret_cast<const uint4*>(Al + o);
            }
#pragma unroll
            for (int nt = 0; nt < 4; nt++) {
                int ntg = wn * 4 + nt;
                int o = ((ntg * 4 + ks) * 32 + lane) * 2;
                bh[nt] = *reinterpret_cast<const uint2*>(Bh + o);
                bl[nt] = *reinterpret_cast<const uint2*>(Bl + o);
            }
#pragma unroll
            for (int mt = 0; mt < 4; mt++)
#pragma unroll
                for (int nt = 0; nt < 4; nt++) {
                    MMA8(acc[mt][nt], ah[mt], bh[nt]);
                    MMA8(acc[mt][nt], ah[mt], bl[nt]);
                    MMA8(acc[mt][nt], al[mt], bh[nt]);
                }
        }

        if (c + 1 < CH) store_smem(1 - p);
        __syncthreads();
    }

    // epilogue: direct stores + bias
#pragma unroll
    for (int mt = 0; mt < 4; mt++) {
        int mrow = m0 + wm * 64 + mt * 16 + (lane >> 2);
#pragma unroll
        for (int half = 0; half < 2; half++) {
            int mg = mrow + half * 8;
            if (mg < Mtot) {
                float bi = bias[mg];
                float* crow = Cb + (size_t)mg * NPTS + n0 + wn * 32 + (lane & 3) * 2;
#pragma unroll
                for (int nt = 0; nt < 4; nt++) {
                    float2 vv;
                    vv.x = acc[mt][nt][half * 2 + 0] + bi;
                    vv.y = acc[mt][nt][half * 2 + 1] + bi;
                    *reinterpret_cast<float2*>(crow + nt * 8) = vv;
                }
            }
        }
    }
}

// ================= remaining fp32 kernels =================
__global__ void init_kernel() {
    int i = blockIdx.x * blockDim.x + threadIdx.x;
    if (i < 2*BB*NPTS) g_u[i] = 0.0f;
    if (i < 2*BB*KK)   g_v[i] = 0.0f;
    if (i < 4)         g_acc[i] = 0.0f;
}

__global__ void bn_stats_kernel(const float* __restrict__ y,
                                const float* __restrict__ g, const float* __restrict__ be,
                                float* __restrict__ sc, float* __restrict__ sh)
{
    int h = blockIdx.x;
    int tid = threadIdx.x;
    float s = 0.0f, s2 = 0.0f;
    for (int b = 0; b < BB; b++) {
        const float* p = y + ((size_t)(b*HH + h)) * NPTS;
        for (int n = tid; n < NPTS; n += 256) { float v = p[n]; s += v; s2 += v*v; }
    }
    __shared__ float r1[256], r2[256];
    r1[tid] = s; r2[tid] = s2; __syncthreads();
    for (int o = 128; o > 0; o >>= 1) {
        if (tid < o) { r1[tid] += r1[tid+o]; r2[tid] += r2[tid+o]; }
        __syncthreads();
    }
    if (tid == 0) {
        float inv = 1.0f / (float)(BB*NPTS);
        float mean = r1[0] * inv;
        float var  = r2[0] * inv - mean*mean;
        float scale = g[h] / sqrtf(var + 1e-5f);
        sc[h] = scale;
        sh[h] = be[h] - mean * scale;
    }
}

__global__ void bn_relu_kernel(float* __restrict__ y,
                               const float* __restrict__ sc, const float* __restrict__ sh)
{
    size_t i4 = (size_t)blockIdx.x * blockDim.x + threadIdx.x;
    size_t total4 = (size_t)BB*HH*NPTS/4;
    if (i4 >= total4) return;
    int h = (int)((i4 / (NPTS/4)) % HH);
    float s = sc[h], t = sh[h];
    float4 v = ((float4*)y)[i4];
    v.x = fmaxf(0.0f, v.x*s + t);
    v.y = fmaxf(0.0f, v.y*s + t);
    v.z = fmaxf(0.0f, v.z*s + t);
    v.w = fmaxf(0.0f, v.w*s + t);
    ((float4*)y)[i4] = v;
}

__global__ void softmax_kernel() {
    int b = blockIdx.y;
    int n = blockIdx.x * 256 + threadIdx.x;
    const float* base = g_ls + (size_t)b*KK*NPTS + n;
    float mx = -1e30f;
#pragma unroll
    for (int k = 0; k < KK; k++) mx = fmaxf(mx, base[(size_t)k*NPTS]);
    float s = 0.0f;
#pragma unroll
    for (int k = 0; k < KK; k++) s += __expf(base[(size_t)k*NPTS] - mx);
    float inv = 1.0f / s;
    float* sb = g_score + (size_t)b*KK*NPTS + n;
#pragma unroll
    for (int k = 0; k < KK; k++) sb[(size_t)k*NPTS] = __expf(base[(size_t)k*NPTS] - mx) * inv;
    g_lsn[b*NPTS + n] = mx + logf(s);
}

__global__ void pi_kernel() {
    int k = blockIdx.x, b = blockIdx.y, tid = threadIdx.x;
    const float* p = g_score + (size_t)(b*KK + k) * NPTS;
    float s = 0.0f;
    for (int n = tid; n < NPTS; n += 256) s += p[n];
    __shared__ float r[256];
    r[tid] = s; __syncthreads();
    for (int o = 128; o > 0; o >>= 1) { if (tid < o) r[tid] += r[tid+o]; __syncthreads(); }
    if (tid == 0) g_pi[b*KK + k] = fmaxf(r[0], 1e-4f);
}

__global__ void mu_xyz_kernel(const float* __restrict__ xyz) {
    int k = blockIdx.x, b = blockIdx.y, tid = threadIdx.x;
    const float* sp = g_score + (size_t)(b*KK + k) * NPTS;
    const float* x0 = xyz + (size_t)(b*3 + 0) * NPTS;
    const float* x1 = xyz + (size_t)(b*3 + 1) * NPTS;
    const float* x2 = xyz + (size_t)(b*3 + 2) * NPTS;
    float a0 = 0, a1 = 0, a2 = 0;
    for (int n = tid; n < NPTS; n += 256) {
        float s = sp[n];
        a0 += s * x0[n]; a1 += s * x1[n]; a2 += s * x2[n];
    }
    __shared__ float r[256];
    float acc[3] = {a0, a1, a2};
    for (int d = 0; d < 3; d++) {
        r[tid] = acc[d]; __syncthreads();
        for (int o = 128; o > 0; o >>= 1) { if (tid < o) r[tid] += r[tid+o]; __syncthreads(); }
        if (tid == 0) {
            float invpi = 1.0f / g_pi[b*KK + k];
            g_muxyz[(b*3 + d)*KK + k] = r[0] * invpi;
        }
        __syncthreads();
    }
}

__global__ __launch_bounds__(256) void mufea_kernel(const float* __restrict__ feat) {
    int b = blockIdx.y;
    int d0 = blockIdx.x * 64;
    __shared__ float Fs[32][65];
    __shared__ float Ss[32][65];
    int tid = threadIdx.x;
    int tx = tid % 16, ty = tid / 16;
    float acc[4][4];
#pragma unroll
    for (int i = 0; i < 4; i++)
#pragma unroll
        for (int j = 0; j < 4; j++) acc[i][j] = 0.0f;

    for (int n0 = 0; n0 < NPTS; n0 += 32) {
#pragma unroll 8
        for (int i = tid; i < 64*32; i += 256) {
            int dd = i / 32, nn = i % 32;
            Fs[nn][dd] = feat[((size_t)b*DD + d0 + dd) * NPTS + n0 + nn];
        }
#pragma unroll 8
        for (int i = tid; i < 64*32; i += 256) {
            int kk = i / 32, nn = i % 32;
            Ss[nn][kk] = g_score[((size_t)b*KK + kk) * NPTS + n0 + nn];
        }
        __syncthreads();
#pragma unroll
        for (int nn = 0; nn < 32; nn++) {
            float a[4], s[4];
#pragma unroll
            for (int i = 0; i < 4; i++) a[i] = Fs[nn][ty*4 + i];
#pragma unroll
            for (int j = 0; j < 4; j++) s[j] = Ss[nn][tx*4 + j];
#pragma unroll
            for (int i = 0; i < 4; i++)
#pragma unroll
                for (int j = 0; j < 4; j++) acc[i][j] += a[i] * s[j];
        }
        __syncthreads();
    }
#pragma unroll
    for (int i = 0; i < 4; i++)
#pragma unroll
        for (int j = 0; j < 4; j++) {
            int k = tx*4 + j;
            g_mufea[((size_t)b*DD + d0 + ty*4 + i) * KK + k] = acc[i][j] / g_pi[b*KK + k];
        }
}

__global__ void invf_kernel(const float* __restrict__ feat) {
    int b = blockIdx.y;
    int n = blockIdx.x * 256 + threadIdx.x;
    float s = 0.0f;
    const float* p = feat + (size_t)b*DD*NPTS + n;
    for (int d = 0; d < DD; d++) { float v = p[(size_t)d*NPTS]; s += v*v; }
    g_invf[b*NPTS + n] = 1.0f / fmaxf(sqrtf(s), 1e-12f);
}

__global__ void invmu_kernel() {
    int b = blockIdx.x, k = threadIdx.x;
    float s = 0.0f;
    const float* p = g_mufea + (size_t)b*DD*KK + k;
    for (int d = 0; d < DD; d++) { float v = p[(size_t)d*KK]; s += v*v; }
    g_invmu[b*KK + k] = 1.0f / fmaxf(sqrtf(s), 1e-12f);
}

__global__ __launch_bounds__(256) void costf_kernel(const float* __restrict__ feat) {
    int b = blockIdx.y;
    int n0 = blockIdx.x * 128;
    __shared__ float As[16][128];
    __shared__ float Bs[16][64];
    int tid = threadIdx.x;
    int tn = tid % 16, tm = tid / 16;
    float acc[8][4];
#pragma unroll
    for (int i = 0; i < 8; i++)
#pragma unroll
        for (int j = 0; j < 4; j++) acc[i][j] = 0.0f;

    for (int d0 = 0; d0 < DD; d0 += 16) {
#pragma unroll 8
        for (int i = tid; i < 16*128; i += 256) {
            int dd = i / 128, nn = i % 128;
            As[dd][nn] = feat[((size_t)b*DD + d0 + dd) * NPTS + n0 + nn];
        }
#pragma unroll 4
        for (int i = tid; i < 16*64; i += 256) {
            int dd = i / 64, mm = i % 64;
            Bs[dd][mm] = g_mufea[((size_t)b*DD + d0 + dd) * KK + mm];
        }
        __syncthreads();
#pragma unroll
        for (int dd = 0; dd < 16; dd++) {
            float a[8], s[4];
#pragma unroll
            for (int i = 0; i < 8; i++) a[i] = As[dd][tn*8 + i];
#pragma unroll
            for (int j = 0; j < 4; j++) s[j] = Bs[dd][tm*4 + j];
#pragma unroll
            for (int i = 0; i < 8; i++)
#pragma unroll
                for (int j = 0; j < 4; j++) acc[i][j] += a[i] * s[j];
        }
        __syncthreads();
    }
#pragma unroll
    for (int i = 0; i < 8; i++) {
        int n = n0 + tn*8 + i;
        float fi = g_invf[b*NPTS + n];
#pragma unroll
        for (int j = 0; j < 4; j++) {
            int m = tm*4 + j;
            g_costf[((size_t)b*NPTS + n) * KK + m] =
                2.0f - 2.0f * acc[i][j] * fi * g_invmu[b*KK + m];
        }
    }
}

__global__ void costx_kernel(const float* __restrict__ xyz) {
    int b = blockIdx.y;
    __shared__ float smu[3][64];
    __shared__ float smun[64];
    int tid = threadIdx.x;
    if (tid < 192) smu[tid/64][tid%64] = g_muxyz[b*3*KK + tid];
    __syncthreads();
    if (tid < 64) smun[tid] = smu[0][tid]*smu[0][tid] + smu[1][tid]*smu[1][tid] + smu[2][tid]*smu[2][tid];
    __syncthreads();
    int w = tid >> 5, l = tid & 31;
    int n = blockIdx.x * 8 + w;
    float x0 = xyz[(size_t)(b*3 + 0)*NPTS + n];
    float x1 = xyz[(size_t)(b*3 + 1)*NPTS + n];
    float x2 = xyz[(size_t)(b*3 + 2)*NPTS + n];
    float xn = x0*x0 + x1*x1 + x2*x2;
    float* row = g_costx + ((size_t)b*NPTS + n) * KK;
#pragma unroll
    for (int t = 0; t < 2; t++) {
        int m = l + t*32;
        float d = x0*smu[0][m] + x1*smu[1][m] + x2*smu[2][m];
        row[m] = xn + smun[m] - 2.0f * d;
    }
}

__global__ void transpose_kernel(const float* __restrict__ src, float* __restrict__ dst) {
    __shared__ float t[32][33];
    int b = blockIdx.z;
    int n0 = blockIdx.x * 32, m0 = blockIdx.y * 32;
    int x = threadIdx.x, y = threadIdx.y;
    for (int j = y; j < 32; j += 8)
        t[j][x] = src[((size_t)b*NPTS + n0 + j) * KK + m0 + x];
    __syncthreads();
    for (int j = y; j < 32; j += 8)
        dst[((size_t)b*KK + m0 + j) * NPTS + n0 + x] = t[x][j];
}

__global__ void u_update_kernel() {
    int branch = blockIdx.y;
    const float* C = branch ? g_costf : g_costx;
    const float* v = (branch ? g_v + BB*KK : g_v);
    float* u = (branch ? g_u + BB*NPTS : g_u);
    int r0 = blockIdx.x * 8;
    int b = r0 >> 12;
    __shared__ float vs[64];
    if (threadIdx.x < 64) vs[threadIdx.x] = v[b*KK + threadIdx.x];
    __syncthreads();
    int w = threadIdx.x >> 5, l = threadIdx.x & 31;
    int r = r0 + w;
    const float* Crow = C + (size_t)r * KK;
    float a0 = (vs[l]      - Crow[l])      * INV_EPS;
    float a1 = (vs[l + 32] - Crow[l + 32]) * INV_EPS;
    float mx = fmaxf(a0, a1);
#pragma unroll
    for (int o = 16; o > 0; o >>= 1) mx = fmaxf(mx, __shfl_xor_sync(0xffffffffu, mx, o));
    float s = __expf(a0 - mx) + __expf(a1 - mx);
#pragma unroll
    for (int o = 16; o > 0; o >>= 1) s += __shfl_xor_sync(0xffffffffu, s, o);
    if (l == 0) {
        float epslogp = -SEPS * logf((float)NPTS);
        u[r] = epslogp - SEPS * (mx + logf(s));
    }
}

__global__ void v_update_kernel() {
    int branch = blockIdx.y;
    const float* CT = branch ? g_costfT : g_costxT;
    const float* u = (branch ? g_u + BB*NPTS : g_u);
    float* v = (branch ? g_v + BB*KK : g_v);
    int c = blockIdx.x;
    int b = c >> 6;
    const float* row = CT + (size_t)c * NPTS;
    const float* ub = u + b * NPTS;
    int tid = threadIdx.x;
    float vals[16];
    float mx = -1e30f;
#pragma unroll
    for (int i = 0; i < 16; i++) {
        int n = tid + i * 256;
        vals[i] = (ub[n] - row[n]) * INV_EPS;
        mx = fmaxf(mx, vals[i]);
    }
    __shared__ float r[256];
    r[tid] = mx; __syncthreads();
    for (int o = 128; o > 0; o >>= 1) { if (tid < o) r[tid] = fmaxf(r[tid], r[tid+o]); __syncthreads(); }
    mx = r[0]; __syncthreads();
    float s = 0.0f;
#pragma unroll
    for (int i = 0; i < 16; i++) s += __expf(vals[i] - mx);
    r[tid] = s; __syncthreads();
    for (int o = 128; o > 0; o >>= 1) { if (tid < o) r[tid] += r[tid+o]; __syncthreads(); }
    if (tid == 0) {
        float epslogq = -SEPS * logf((float)KK);
        v[c] = epslogq - SEPS * (mx + logf(r[0]));
    }
}

__global__ void reg_xyz_kernel() {
    int b = blockIdx.x, tid = threadIdx.x;
    float local = 0.0f;
    for (int e = tid; e < KK*KK; e += 256) {
        int m1 = e >> 6, m2 = e & 63;
        float s = 0.0f;
#pragma unroll
        for (int d = 0; d < 3; d++)
            s += g_muxyz[(b*3 + d)*KK + m1] * g_muxyz[(b*3 + d)*KK + m2];
        local += fabsf(s - (m1 == m2 ? 1.0f : 0.0f));
    }
    __shared__ float r[256];
    r[tid] = local; __syncthreads();
    for (int o = 128; o > 0; o >>= 1) { if (tid < o) r[tid] += r[tid+o]; __syncthreads(); }
    if (tid == 0) atomicAdd(&g_acc[2], r[0]);
}

__global__ void reg_fea_kernel() {
    int b = blockIdx.x, tid = threadIdx.x;
    float local = 0.0f;
    for (int e = tid; e < KK*KK; e += 256) {
        int m1 = e >> 6, m2 = e & 63;
        const float* p1 = g_mufea + (size_t)b*DD*KK + m1;
        const float* p2 = g_mufea + (size_t)b*DD*KK + m2;
        float s = 0.0f;
#pragma unroll 8
        for (int d = 0; d < DD; d++) s += p1[(size_t)d*KK] * p2[(size_t)d*KK];
        s *= g_invmu[b*KK + m1] * g_invmu[b*KK + m2];
        local += fabsf(s - (m1 == m2 ? 1.0f : 0.0f));
    }
    __shared__ float r[256];
    r[tid] = local; __syncthreads();
    for (int o = 128; o > 0; o >>= 1) { if (tid < o) r[tid] += r[tid+o]; __syncthreads(); }
    if (tid == 0) atomicAdd(&g_acc[3], r[0]);
}

__global__ void loss_kernel() {
    int branch = blockIdx.y;
    const float* C = branch ? g_costf : g_costx;
    const float* u = (branch ? g_u + BB*NPTS : g_u);
    const float* v = (branch ? g_v + BB*KK : g_v);
    int r0 = blockIdx.x * 8;
    int b = r0 >> 12;
    __shared__ float vs[64];
    if (threadIdx.x < 64) vs[threadIdx.x] = v[b*KK + threadIdx.x];
    __syncthreads();
    int w = threadIdx.x >> 5, l = threadIdx.x & 31;
    int r = r0 + w;
    int n = r & (NPTS - 1);
    const float* Crow = C + (size_t)r * KK;
    float ur = u[r];
    float lsnr = g_lsn[r];
    float acc = 0.0f;
#pragma unroll
    for (int t = 0; t < 2; t++) {
        int m = l + t*32;
        float gma = __expf((ur + vs[m] - Crow[m]) * INV_EPS);
        float lp = g_ls[((size_t)b*KK + m) * NPTS + n] - lsnr;
        acc += gma * lp;
    }
#pragma unroll
    for (int o = 16; o > 0; o >>= 1) acc += __shfl_xor_sync(0xffffffffu, acc, o);
    __shared__ float wsum[8];
    if (l == 0) wsum[w] = acc;
    __syncthreads();
    if (threadIdx.x == 0) {
        float t = 0.0f;
#pragma unroll
        for (int i = 0; i < 8; i++) t += wsum[i];
        atomicAdd(&g_acc[branch], t);
    }
}

__global__ void finalize_kernel(float* __restrict__ out, int out_size) {
    int i = threadIdx.x;
    for (int j = i; j < out_size; j += 32) out[j] = 0.0f;
    __syncwarp();
    if (i == 0) {
        float lx = g_acc[0], lf = g_acc[1], rx = g_acc[2], rf = g_acc[3];
        float loss_xyz = -lx / 8.0f;
        float loss_fea = -lf / 8.0f;
        float reg_fea  = 1e-4f * (rf / (float)(BB*KK*KK));
        float reg_xyz  = 0.001f * 1e-4f * (rx / (float)(BB*KK*KK));
        out[0] = loss_xyz + loss_fea + reg_fea + reg_xyz;
    }
}

// ---------------- launch ----------------
extern "C" void kernel_launch(void* const* d_in, const int* in_sizes, int n_in,
                              void* d_out, int out_size)
{
    const float* feature = (const float*)d_in[0];
    const float* xyz     = (const float*)d_in[1];
    const float* w1      = (const float*)d_in[2];
    const float* b1      = (const float*)d_in[3];
    const float* g1      = (const float*)d_in[4];
    const float* be1     = (const float*)d_in[5];
    const float* w2      = (const float*)d_in[6];
    const float* b2      = (const float*)d_in[7];
    const float* g2      = (const float*)d_in[8];
    const float* be2     = (const float*)d_in[9];
    const float* w3      = (const float*)d_in[10];
    const float* b3      = (const float*)d_in[11];
    float* out = (float*)d_out;

    float* y1 = nullptr; float* y2 = nullptr; float* ls = nullptr;
    cudaGetSymbolAddress((void**)&y1, g_y1);
    cudaGetSymbolAddress((void**)&y2, g_y2);
    cudaGetSymbolAddress((void**)&ls, g_ls);
    float* sc1; float* sh1; float* sc2; float* sh2;
    cudaGetSymbolAddress((void**)&sc1, g_sc1);
    cudaGetSymbolAddress((void**)&sh1, g_sh1);
    cudaGetSymbolAddress((void**)&sc2, g_sc2);
    cudaGetSymbolAddress((void**)&sh2, g_sh2);
    float* cx; float* cxT; float* cf; float* cfT;
    cudaGetSymbolAddress((void**)&cx,  g_costx);
    cudaGetSymbolAddress((void**)&cxT, g_costxT);
    cudaGetSymbolAddress((void**)&cf,  g_costf);
    cudaGetSymbolAddress((void**)&cfT, g_costfT);

    static int smem_set = 0;
    if (!smem_set) {
        cudaFuncSetAttribute(mma_gemm_kernel, cudaFuncAttributeMaxDynamicSharedMemorySize, (int)GEMM_SMEM);
        smem_set = 1;
    }

    init_kernel<<<(2*BB*NPTS + 255)/256, 256>>>();

    // layer 1: [512,1024] x [1024,4096]
    mma_gemm_kernel<<<dim3(NPTS/128, HH/128, BB), 256, GEMM_SMEM>>>(w1, feature, b1, y1, DD, HH);
    bn_stats_kernel<<<HH, 256>>>(y1, g1, be1, sc1, sh1);
    bn_relu_kernel<<<(BB*HH*NPTS/4 + 255)/256, 256>>>(y1, sc1, sh1);
    // layer 2: [512,512]
    mma_gemm_kernel<<<dim3(NPTS/128, HH/128, BB), 256, GEMM_SMEM>>>(w2, y1, b2, y2, HH, HH);
    bn_stats_kernel<<<HH, 256>>>(y2, g2, be2, sc2, sh2);
    bn_relu_kernel<<<(BB*HH*NPTS/4 + 255)/256, 256>>>(y2, sc2, sh2);
    // layer 3: [64,512] (M padded to 128 by row duplication inside)
    mma_gemm_kernel<<<dim3(NPTS/128, 1, BB), 256, GEMM_SMEM>>>(w3, y2, b3, ls, HH, KK);

    softmax_kernel<<<dim3(NPTS/256, BB), 256>>>();
    pi_kernel<<<dim3(KK, BB), 256>>>();
    mu_xyz_kernel<<<dim3(KK, BB), 256>>>(xyz);
    mufea_kernel<<<dim3(DD/64, BB), 256>>>(feature);
    invf_kernel<<<dim3(NPTS/256, BB), 256>>>(feature);
    invmu_kernel<<<BB, 64>>>();
    costf_kernel<<<dim3(NPTS/128, BB), 256>>>(feature);
    costx_kernel<<<dim3(NPTS/8, BB), 256>>>(xyz);
    transpose_kernel<<<dim3(NPTS/32, KK/32, BB), dim3(32, 8)>>>(cx, cxT);
    transpose_kernel<<<dim3(NPTS/32, KK/32, BB), dim3(32, 8)>>>(cf, cfT);

    for (int it = 0; it < 25; it++) {
        u_update_kernel<<<dim3(BB*NPTS/8, 2), 256>>>();
        v_update_kernel<<<dim3(BB*KK, 2), 256>>>();
    }

    reg_xyz_kernel<<<BB, 256>>>();
    reg_fea_kernel<<<BB, 256>>>();
    loss_kernel<<<dim3(BB*NPTS/8, 2), 256>>>();
    finalize_kernel<<<1, 32>>>(out, out_size);
}

// round 9
// speedup vs baseline: 1.2254x; 1.2254x over previous
#include <cuda_runtime.h>
#include <math.h>
#include <stdint.h>

#define BB   8
#define DD   1024
#define NPTS 4096
#define KK   64
#define HH   512

#define SEPS 1e-3f
#define INV_EPS (1.0f/1e-3f)

// ---------------- scratch (device globals; no allocation) ----------------
static __device__ float g_y1[BB*HH*NPTS];      // 64MB
static __device__ float g_y2[BB*HH*NPTS];      // 64MB
static __device__ float g_ls[BB*KK*NPTS];      // 8MB  log_score
static __device__ float g_score[BB*KK*NPTS];   // 8MB
static __device__ float g_lsn[BB*NPTS];
static __device__ float g_pi[BB*KK];
static __device__ float g_sc1[HH], g_sh1[HH], g_sc2[HH], g_sh2[HH];
static __device__ float g_muxyz[BB*3*KK];
static __device__ float g_mufea[BB*DD*KK];
static __device__ float g_invf[BB*NPTS];
static __device__ float g_invmu[BB*KK];
static __device__ float g_costx[BB*NPTS*KK];
static __device__ float g_costxT[BB*KK*NPTS];
static __device__ float g_costf[BB*NPTS*KK];
static __device__ float g_costfT[BB*KK*NPTS];
static __device__ float g_u[2*BB*NPTS];
static __device__ float g_v[2*BB*KK];
static __device__ float g_acc[4];

// ================= 3xTF32 GEMM via mma.sync =================
// C[b][m][n] = sum_k W[m][k] * X[b][k][n] + bias[m]
// CTA tile 128Mx128N, BK=16, double buffered (2 x 32KB smem = 64KB -> 2 CTA/SM).
// 8 warps: wm=wid>>2 (2), wn=wid&3 (4); warp tile 64x32 = 4x4 m16n8k8 tiles.
// SMEM fragment order per buffer (words):
//   Ah[0:2048) Al[2048:4096) Bh[4096:6144) Bl[6144:8192)
//   A word = (( (m>>4)*2 + (kk>>3) )<<7) + (((m&7)*4+(kk&3))<<2) + ((m>>3)&1) + (((kk>>2)&1)<<1)
//   B word = (( (n>>3)*2 + (kk>>3) )<<6) + (((n&7)*4+(kk&3))<<1) + ((kk>>2)&1)

__device__ __forceinline__ void and_split(float x, uint32_t& h, uint32_t& l) {
    uint32_t xi = __float_as_uint(x);
    h = xi & 0xffffe000u;
    l = __float_as_uint(x - __uint_as_float(h));
}

#define MMA8(d, a, b) \
    asm volatile("mma.sync.aligned.m16n8k8.row.col.f32.tf32.tf32.f32 " \
        "{%0,%1,%2,%3}, {%4,%5,%6,%7}, {%8,%9}, {%0,%1,%2,%3};" \
        : "+f"((d)[0]), "+f"((d)[1]), "+f"((d)[2]), "+f"((d)[3]) \
        : "r"((a).x), "r"((a).y), "r"((a).z), "r"((a).w), "r"((b).x), "r"((b).y))

#define GEMM_SMEM (2 * 8192 * sizeof(uint32_t))   // 64 KB

__global__ __launch_bounds__(256, 2)
void mma_gemm_kernel(const float* __restrict__ W, const float* __restrict__ X,
                     const float* __restrict__ bias, float* __restrict__ C,
                     int Kd, int Mtot)
{
    extern __shared__ uint32_t sm[];
    const int tid = threadIdx.x, wid = tid >> 5, lane = tid & 31;
    const int wm = wid >> 2, wn = wid & 3;
    const int b = blockIdx.z, n0 = blockIdx.x * 128, m0 = blockIdx.y * 128;
    const float* Xb = X + (size_t)b * Kd * NPTS;
    float* Cb = C + (size_t)b * Mtot * NPTS;

    float acc[4][4][4];
#pragma unroll
    for (int i = 0; i < 4; i++)
#pragma unroll
        for (int j = 0; j < 4; j++)
#pragma unroll
            for (int r = 0; r < 4; r++) acc[i][j][r] = 0.0f;

    const int CH = Kd / 16;

    // ---- staging task decomposition ----
    const int a_ks = tid & 1, a_r8 = (tid >> 1) & 7, a_mt = tid >> 4;
    const int a_m = a_mt * 16 + a_r8;
    const int t2 = tid - 128;

    float4 r0a, r0b, r1a, r1b;     // A staging regs
    float4 v0[2], v1[2];           // B staging regs

    auto ldg_regs = [&](int k0) {
        if (tid < 128) {
            int ms0 = m0 + a_m;     if (ms0 >= Mtot) ms0 -= Mtot;
            int ms1 = m0 + a_m + 8; if (ms1 >= Mtot) ms1 -= Mtot;
            const float* p0 = W + (size_t)ms0 * Kd + k0 + a_ks * 8;
            const float* p1 = W + (size_t)ms1 * Kd + k0 + a_ks * 8;
            r0a = *(const float4*)(p0);
            r0b = *(const float4*)(p0 + 4);
            r1a = *(const float4*)(p1);
            r1b = *(const float4*)(p1 + 4);
        } else {
#pragma unroll
            for (int s = 0; s < 2; s++) {
                int task = t2 + s * 128;
                int kp = task >> 5, nq = task & 31;
                int kk = (kp & 3) + ((kp >> 2) << 3);
                const float* p = Xb + (size_t)(k0 + kk) * NPTS + n0 + nq * 4;
                v0[s] = *(const float4*)(p);
                v1[s] = *(const float4*)(p + 4 * (size_t)NPTS);
            }
        }
    };

    auto sts_smem = [&](int buf) {
        uint32_t* Ah = sm + buf * 8192;
        uint32_t* Al = Ah + 2048;
        uint32_t* Bh = Ah + 4096;
        uint32_t* Bl = Ah + 6144;
        if (tid < 128) {
            int base = (a_mt * 2 + a_ks) * 128 + a_r8 * 16;
            const float* q0a = (const float*)&r0a;
            const float* q0b = (const float*)&r0b;
            const float* q1a = (const float*)&r1a;
            const float* q1b = (const float*)&r1b;
#pragma unroll
            for (int j = 0; j < 4; j++) {
                uint32_t h0,h1,h2,h3,l0,l1,l2,l3;
                and_split(q0a[j], h0, l0);   // (m,   kk)
                and_split(q1a[j], h1, l1);   // (m+8, kk)
                and_split(q0b[j], h2, l2);   // (m,   kk+4)
                and_split(q1b[j], h3, l3);   // (m+8, kk+4)
                *(uint4*)(Ah + base + j * 4) = make_uint4(h0, h1, h2, h3);
                *(uint4*)(Al + base + j * 4) = make_uint4(l0, l1, l2, l3);
            }
        } else {
#pragma unroll
            for (int s = 0; s < 2; s++) {
                int task = t2 + s * 128;
                int kp = task >> 5, nq = task & 31;
                int kk = (kp & 3) + ((kp >> 2) << 3);
                const float* a0 = (const float*)&v0[s];
                const float* a1 = (const float*)&v1[s];
#pragma unroll
                for (int j = 0; j < 4; j++) {
                    int n = nq * 4 + j;
                    uint32_t h0, l0, h1, l1;
                    and_split(a0[j], h0, l0);   // (kk,   n)
                    and_split(a1[j], h1, l1);   // (kk+4, n)
                    int w = ((n >> 3) * 2 + (kk >> 3)) * 64 + ((n & 7) * 4 + (kk & 3)) * 2;
                    *(uint2*)(Bh + w) = make_uint2(h0, h1);
                    *(uint2*)(Bl + w) = make_uint2(l0, l1);
                }
            }
        }
    };

    // prologue
    ldg_regs(0);
    sts_smem(0);
    __syncthreads();

    for (int c = 0; c < CH; c++) {
        int p = c & 1;
        if (c + 1 < CH) ldg_regs((c + 1) * 16);

        const uint32_t* Ah = sm + p * 8192;
        const uint32_t* Al = Ah + 2048;
        const uint32_t* Bh = Ah + 4096;
        const uint32_t* Bl = Ah + 6144;

#pragma unroll
        for (int ks = 0; ks < 2; ks++) {
            uint4 ah[4], al[4];
            uint2 bh[4], bl[4];
#pragma unroll
            for (int mt = 0; mt < 4; mt++) {
                int o = (((wm * 4 + mt) * 2 + ks) * 32 + lane) * 4;
                ah[mt] = *(const uint4*)(Ah + o);
                al[mt] = *(const uint4*)(Al + o);
            }
#pragma unroll
            for (int nt = 0; nt < 4; nt++) {
                int o = (((wn * 4 + nt) * 2 + ks) * 32 + lane) * 2;
                bh[nt] = *(const uint2*)(Bh + o);
                bl[nt] = *(const uint2*)(Bl + o);
            }
#pragma unroll
            for (int mt = 0; mt < 4; mt++)
#pragma unroll
                for (int nt = 0; nt < 4; nt++) {
                    MMA8(acc[mt][nt], ah[mt], bh[nt]);
                    MMA8(acc[mt][nt], ah[mt], bl[nt]);
                    MMA8(acc[mt][nt], al[mt], bh[nt]);
                }
        }

        if (c + 1 < CH) sts_smem(1 - p);
        __syncthreads();
    }

    // epilogue: direct stores + bias
#pragma unroll
    for (int mt = 0; mt < 4; mt++) {
        int mrow = m0 + wm * 64 + mt * 16 + (lane >> 2);
#pragma unroll
        for (int half = 0; half < 2; half++) {
            int mg = mrow + half * 8;
            if (mg < Mtot) {
                float bi = bias[mg];
                float* crow = Cb + (size_t)mg * NPTS + n0 + wn * 32 + (lane & 3) * 2;
#pragma unroll
                for (int nt = 0; nt < 4; nt++) {
                    float2 vv;
                    vv.x = acc[mt][nt][half * 2 + 0] + bi;
                    vv.y = acc[mt][nt][half * 2 + 1] + bi;
                    *(float2*)(crow + nt * 8) = vv;
                }
            }
        }
    }
}

// ================= remaining fp32 kernels =================
__global__ void init_kernel() {
    int i = blockIdx.x * blockDim.x + threadIdx.x;
    if (i < 2*BB*NPTS) g_u[i] = 0.0f;
    if (i < 2*BB*KK)   g_v[i] = 0.0f;
    if (i < 4)         g_acc[i] = 0.0f;
}

__global__ void bn_stats_kernel(const float* __restrict__ y,
                                const float* __restrict__ g, const float* __restrict__ be,
                                float* __restrict__ sc, float* __restrict__ sh)
{
    int h = blockIdx.x;
    int tid = threadIdx.x;
    float s = 0.0f, s2 = 0.0f;
    for (int b = 0; b < BB; b++) {
        const float* p = y + ((size_t)(b*HH + h)) * NPTS;
        for (int n = tid; n < NPTS; n += 256) { float v = p[n]; s += v; s2 += v*v; }
    }
    __shared__ float r1[256], r2[256];
    r1[tid] = s; r2[tid] = s2; __syncthreads();
    for (int o = 128; o > 0; o >>= 1) {
        if (tid < o) { r1[tid] += r1[tid+o]; r2[tid] += r2[tid+o]; }
        __syncthreads();
    }
    if (tid == 0) {
        float inv = 1.0f / (float)(BB*NPTS);
        float mean = r1[0] * inv;
        float var  = r2[0] * inv - mean*mean;
        float scale = g[h] / sqrtf(var + 1e-5f);
        sc[h] = scale;
        sh[h] = be[h] - mean * scale;
    }
}

__global__ void bn_relu_kernel(float* __restrict__ y,
                               const float* __restrict__ sc, const float* __restrict__ sh)
{
    size_t i4 = (size_t)blockIdx.x * blockDim.x + threadIdx.x;
    size_t total4 = (size_t)BB*HH*NPTS/4;
    if (i4 >= total4) return;
    int h = (int)((i4 / (NPTS/4)) % HH);
    float s = sc[h], t = sh[h];
    float4 v = ((float4*)y)[i4];
    v.x = fmaxf(0.0f, v.x*s + t);
    v.y = fmaxf(0.0f, v.y*s + t);
    v.z = fmaxf(0.0f, v.z*s + t);
    v.w = fmaxf(0.0f, v.w*s + t);
    ((float4*)y)[i4] = v;
}

__global__ void softmax_kernel() {
    int b = blockIdx.y;
    int n = blockIdx.x * 256 + threadIdx.x;
    const float* base = g_ls + (size_t)b*KK*NPTS + n;
    float mx = -1e30f;
#pragma unroll
    for (int k = 0; k < KK; k++) mx = fmaxf(mx, base[(size_t)k*NPTS]);
    float s = 0.0f;
#pragma unroll
    for (int k = 0; k < KK; k++) s += __expf(base[(size_t)k*NPTS] - mx);
    float inv = 1.0f / s;
    float* sb = g_score + (size_t)b*KK*NPTS + n;
#pragma unroll
    for (int k = 0; k < KK; k++) sb[(size_t)k*NPTS] = __expf(base[(size_t)k*NPTS] - mx) * inv;
    g_lsn[b*NPTS + n] = mx + logf(s);
}

__global__ void pi_kernel() {
    int k = blockIdx.x, b = blockIdx.y, tid = threadIdx.x;
    const float* p = g_score + (size_t)(b*KK + k) * NPTS;
    float s = 0.0f;
    for (int n = tid; n < NPTS; n += 256) s += p[n];
    __shared__ float r[256];
    r[tid] = s; __syncthreads();
    for (int o = 128; o > 0; o >>= 1) { if (tid < o) r[tid] += r[tid+o]; __syncthreads(); }
    if (tid == 0) g_pi[b*KK + k] = fmaxf(r[0], 1e-4f);
}

__global__ void mu_xyz_kernel(const float* __restrict__ xyz) {
    int k = blockIdx.x, b = blockIdx.y, tid = threadIdx.x;
    const float* sp = g_score + (size_t)(b*KK + k) * NPTS;
    const float* x0 = xyz + (size_t)(b*3 + 0) * NPTS;
    const float* x1 = xyz + (size_t)(b*3 + 1) * NPTS;
    const float* x2 = xyz + (size_t)(b*3 + 2) * NPTS;
    float a0 = 0, a1 = 0, a2 = 0;
    for (int n = tid; n < NPTS; n += 256) {
        float s = sp[n];
        a0 += s * x0[n]; a1 += s * x1[n]; a2 += s * x2[n];
    }
    __shared__ float r[256];
    float acc[3] = {a0, a1, a2};
    for (int d = 0; d < 3; d++) {
        r[tid] = acc[d]; __syncthreads();
        for (int o = 128; o > 0; o >>= 1) { if (tid < o) r[tid] += r[tid+o]; __syncthreads(); }
        if (tid == 0) {
            float invpi = 1.0f / g_pi[b*KK + k];
            g_muxyz[(b*3 + d)*KK + k] = r[0] * invpi;
        }
        __syncthreads();
    }
}

__global__ __launch_bounds__(256) void mufea_kernel(const float* __restrict__ feat) {
    int b = blockIdx.y;
    int d0 = blockIdx.x * 64;
    __shared__ float Fs[32][65];
    __shared__ float Ss[32][65];
    int tid = threadIdx.x;
    int tx = tid % 16, ty = tid / 16;
    float acc[4][4];
#pragma unroll
    for (int i = 0; i < 4; i++)
#pragma unroll
        for (int j = 0; j < 4; j++) acc[i][j] = 0.0f;

    for (int n0 = 0; n0 < NPTS; n0 += 32) {
#pragma unroll 8
        for (int i = tid; i < 64*32; i += 256) {
            int dd = i / 32, nn = i % 32;
            Fs[nn][dd] = feat[((size_t)b*DD + d0 + dd) * NPTS + n0 + nn];
        }
#pragma unroll 8
        for (int i = tid; i < 64*32; i += 256) {
            int kk = i / 32, nn = i % 32;
            Ss[nn][kk] = g_score[((size_t)b*KK + kk) * NPTS + n0 + nn];
        }
        __syncthreads();
#pragma unroll
        for (int nn = 0; nn < 32; nn++) {
            float a[4], s[4];
#pragma unroll
            for (int i = 0; i < 4; i++) a[i] = Fs[nn][ty*4 + i];
#pragma unroll
            for (int j = 0; j < 4; j++) s[j] = Ss[nn][tx*4 + j];
#pragma unroll
            for (int i = 0; i < 4; i++)
#pragma unroll
                for (int j = 0; j < 4; j++) acc[i][j] += a[i] * s[j];
        }
        __syncthreads();
    }
#pragma unroll
    for (int i = 0; i < 4; i++)
#pragma unroll
        for (int j = 0; j < 4; j++) {
            int k = tx*4 + j;
            g_mufea[((size_t)b*DD + d0 + ty*4 + i) * KK + k] = acc[i][j] / g_pi[b*KK + k];
        }
}

__global__ void invf_kernel(const float* __restrict__ feat) {
    int b = blockIdx.y;
    int n = blockIdx.x * 256 + threadIdx.x;
    float s = 0.0f;
    const float* p = feat + (size_t)b*DD*NPTS + n;
    for (int d = 0; d < DD; d++) { float v = p[(size_t)d*NPTS]; s += v*v; }
    g_invf[b*NPTS + n] = 1.0f / fmaxf(sqrtf(s), 1e-12f);
}

__global__ void invmu_kernel() {
    int b = blockIdx.x, k = threadIdx.x;
    float s = 0.0f;
    const float* p = g_mufea + (size_t)b*DD*KK + k;
    for (int d = 0; d < DD; d++) { float v = p[(size_t)d*KK]; s += v*v; }
    g_invmu[b*KK + k] = 1.0f / fmaxf(sqrtf(s), 1e-12f);
}

__global__ __launch_bounds__(256) void costf_kernel(const float* __restrict__ feat) {
    int b = blockIdx.y;
    int n0 = blockIdx.x * 128;
    __shared__ float As[16][128];
    __shared__ float Bs[16][64];
    int tid = threadIdx.x;
    int tn = tid % 16, tm = tid / 16;
    float acc[8][4];
#pragma unroll
    for (int i = 0; i < 8; i++)
#pragma unroll
        for (int j = 0; j < 4; j++) acc[i][j] = 0.0f;

    for (int d0 = 0; d0 < DD; d0 += 16) {
#pragma unroll 8
        for (int i = tid; i < 16*128; i += 256) {
            int dd = i / 128, nn = i % 128;
            As[dd][nn] = feat[((size_t)b*DD + d0 + dd) * NPTS + n0 + nn];
        }
#pragma unroll 4
        for (int i = tid; i < 16*64; i += 256) {
            int dd = i / 64, mm = i % 64;
            Bs[dd][mm] = g_mufea[((size_t)b*DD + d0 + dd) * KK + mm];
        }
        __syncthreads();
#pragma unroll
        for (int dd = 0; dd < 16; dd++) {
            float a[8], s[4];
#pragma unroll
            for (int i = 0; i < 8; i++) a[i] = As[dd][tn*8 + i];
#pragma unroll
            for (int j = 0; j < 4; j++) s[j] = Bs[dd][tm*4 + j];
#pragma unroll
            for (int i = 0; i < 8; i++)
#pragma unroll
                for (int j = 0; j < 4; j++) acc[i][j] += a[i] * s[j];
        }
        __syncthreads();
    }
#pragma unroll
    for (int i = 0; i < 8; i++) {
        int n = n0 + tn*8 + i;
        float fi = g_invf[b*NPTS + n];
#pragma unroll
        for (int j = 0; j < 4; j++) {
            int m = tm*4 + j;
            g_costf[((size_t)b*NPTS + n) * KK + m] =
                2.0f - 2.0f * acc[i][j] * fi * g_invmu[b*KK + m];
        }
    }
}

__global__ void costx_kernel(const float* __restrict__ xyz) {
    int b = blockIdx.y;
    __shared__ float smu[3][64];
    __shared__ float smun[64];
    int tid = threadIdx.x;
    if (tid < 192) smu[tid/64][tid%64] = g_muxyz[b*3*KK + tid];
    __syncthreads();
    if (tid < 64) smun[tid] = smu[0][tid]*smu[0][tid] + smu[1][tid]*smu[1][tid] + smu[2][tid]*smu[2][tid];
    __syncthreads();
    int w = tid >> 5, l = tid & 31;
    int n = blockIdx.x * 8 + w;
    float x0 = xyz[(size_t)(b*3 + 0)*NPTS + n];
    float x1 = xyz[(size_t)(b*3 + 1)*NPTS + n];
    float x2 = xyz[(size_t)(b*3 + 2)*NPTS + n];
    float xn = x0*x0 + x1*x1 + x2*x2;
    float* row = g_costx + ((size_t)b*NPTS + n) * KK;
#pragma unroll
    for (int t = 0; t < 2; t++) {
        int m = l + t*32;
        float d = x0*smu[0][m] + x1*smu[1][m] + x2*smu[2][m];
        row[m] = xn + smun[m] - 2.0f * d;
    }
}

__global__ void transpose_kernel(const float* __restrict__ src, float* __restrict__ dst) {
    __shared__ float t[32][33];
    int b = blockIdx.z;
    int n0 = blockIdx.x * 32, m0 = blockIdx.y * 32;
    int x = threadIdx.x, y = threadIdx.y;
    for (int j = y; j < 32; j += 8)
        t[j][x] = src[((size_t)b*NPTS + n0 + j) * KK + m0 + x];
    __syncthreads();
    for (int j = y; j < 32; j += 8)
        dst[((size_t)b*KK + m0 + j) * NPTS + n0 + x] = t[x][j];
}

__global__ void u_update_kernel() {
    int branch = blockIdx.y;
    const float* C = branch ? g_costf : g_costx;
    const float* v = (branch ? g_v + BB*KK : g_v);
    float* u = (branch ? g_u + BB*NPTS : g_u);
    int r0 = blockIdx.x * 8;
    int b = r0 >> 12;
    __shared__ float vs[64];
    if (threadIdx.x < 64) vs[threadIdx.x] = v[b*KK + threadIdx.x];
    __syncthreads();
    int w = threadIdx.x >> 5, l = threadIdx.x & 31;
    int r = r0 + w;
    const float* Crow = C + (size_t)r * KK;
    float a0 = (vs[l]      - Crow[l])      * INV_EPS;
    float a1 = (vs[l + 32] - Crow[l + 32]) * INV_EPS;
    float mx = fmaxf(a0, a1);
#pragma unroll
    for (int o = 16; o > 0; o >>= 1) mx = fmaxf(mx, __shfl_xor_sync(0xffffffffu, mx, o));
    float s = __expf(a0 - mx) + __expf(a1 - mx);
#pragma unroll
    for (int o = 16; o > 0; o >>= 1) s += __shfl_xor_sync(0xffffffffu, s, o);
    if (l == 0) {
        float epslogp = -SEPS * logf((float)NPTS);
        u[r] = epslogp - SEPS * (mx + logf(s));
    }
}

__global__ void v_update_kernel() {
    int branch = blockIdx.y;
    const float* CT = branch ? g_costfT : g_costxT;
    const float* u = (branch ? g_u + BB*NPTS : g_u);
    float* v = (branch ? g_v + BB*KK : g_v);
    int c = blockIdx.x;
    int b = c >> 6;
    const float* row = CT + (size_t)c * NPTS;
    const float* ub = u + b * NPTS;
    int tid = threadIdx.x;
    float vals[16];
    float mx = -1e30f;
#pragma unroll
    for (int i = 0; i < 16; i++) {
        int n = tid + i * 256;
        vals[i] = (ub[n] - row[n]) * INV_EPS;
        mx = fmaxf(mx, vals[i]);
    }
    __shared__ float r[256];
    r[tid] = mx; __syncthreads();
    for (int o = 128; o > 0; o >>= 1) { if (tid < o) r[tid] = fmaxf(r[tid], r[tid+o]); __syncthreads(); }
    mx = r[0]; __syncthreads();
    float s = 0.0f;
#pragma unroll
    for (int i = 0; i < 16; i++) s += __expf(vals[i] - mx);
    r[tid] = s; __syncthreads();
    for (int o = 128; o > 0; o >>= 1) { if (tid < o) r[tid] += r[tid+o]; __syncthreads(); }
    if (tid == 0) {
        float epslogq = -SEPS * logf((float)KK);
        v[c] = epslogq - SEPS * (mx + logf(r[0]));
    }
}

__global__ void reg_xyz_kernel() {
    int b = blockIdx.x, tid = threadIdx.x;
    float local = 0.0f;
    for (int e = tid; e < KK*KK; e += 256) {
        int m1 = e >> 6, m2 = e & 63;
        float s = 0.0f;
#pragma unroll
        for (int d = 0; d < 3; d++)
            s += g_muxyz[(b*3 + d)*KK + m1] * g_muxyz[(b*3 + d)*KK + m2];
        local += fabsf(s - (m1 == m2 ? 1.0f : 0.0f));
    }
    __shared__ float r[256];
    r[tid] = local; __syncthreads();
    for (int o = 128; o > 0; o >>= 1) { if (tid < o) r[tid] += r[tid+o]; __syncthreads(); }
    if (tid == 0) atomicAdd(&g_acc[2], r[0]);
}

__global__ void reg_fea_kernel() {
    int b = blockIdx.x, tid = threadIdx.x;
    float local = 0.0f;
    for (int e = tid; e < KK*KK; e += 256) {
        int m1 = e >> 6, m2 = e & 63;
        const float* p1 = g_mufea + (size_t)b*DD*KK + m1;
        const float* p2 = g_mufea + (size_t)b*DD*KK + m2;
        float s = 0.0f;
#pragma unroll 8
        for (int d = 0; d < DD; d++) s += p1[(size_t)d*KK] * p2[(size_t)d*KK];
        s *= g_invmu[b*KK + m1] * g_invmu[b*KK + m2];
        local += fabsf(s - (m1 == m2 ? 1.0f : 0.0f));
    }
    __shared__ float r[256];
    r[tid] = local; __syncthreads();
    for (int o = 128; o > 0; o >>= 1) { if (tid < o) r[tid] += r[tid+o]; __syncthreads(); }
    if (tid == 0) atomicAdd(&g_acc[3], r[0]);
}

__global__ void loss_kernel() {
    int branch = blockIdx.y;
    const float* C = branch ? g_costf : g_costx;
    const float* u = (branch ? g_u + BB*NPTS : g_u);
    const float* v = (branch ? g_v + BB*KK : g_v);
    int r0 = blockIdx.x * 8;
    int b = r0 >> 12;
    __shared__ float vs[64];
    if (threadIdx.x < 64) vs[threadIdx.x] = v[b*KK + threadIdx.x];
    __syncthreads();
    int w = threadIdx.x >> 5, l = threadIdx.x & 31;
    int r = r0 + w;
    int n = r & (NPTS - 1);
    const float* Crow = C + (size_t)r * KK;
    float ur = u[r];
    float lsnr = g_lsn[r];
    float acc = 0.0f;
#pragma unroll
    for (int t = 0; t < 2; t++) {
        int m = l + t*32;
        float gma = __expf((ur + vs[m] - Crow[m]) * INV_EPS);
        float lp = g_ls[((size_t)b*KK + m) * NPTS + n] - lsnr;
        acc += gma * lp;
    }
#pragma unroll
    for (int o = 16; o > 0; o >>= 1) acc += __shfl_xor_sync(0xffffffffu, acc, o);
    __shared__ float wsum[8];
    if (l == 0) wsum[w] = acc;
    __syncthreads();
    if (threadIdx.x == 0) {
        float t = 0.0f;
#pragma unroll
        for (int i = 0; i < 8; i++) t += wsum[i];
        atomicAdd(&g_acc[branch], t);
    }
}

__global__ void finalize_kernel(float* __restrict__ out, int out_size) {
    int i = threadIdx.x;
    for (int j = i; j < out_size; j += 32) out[j] = 0.0f;
    __syncwarp();
    if (i == 0) {
        float lx = g_acc[0], lf = g_acc[1], rx = g_acc[2], rf = g_acc[3];
        float loss_xyz = -lx / 8.0f;
        float loss_fea = -lf / 8.0f;
        float reg_fea  = 1e-4f * (rf / (float)(BB*KK*KK));
        float reg_xyz  = 0.001f * 1e-4f * (rx / (float)(BB*KK*KK));
        out[0] = loss_xyz + loss_fea + reg_fea + reg_xyz;
    }
}

// ---------------- launch ----------------
extern "C" void kernel_launch(void* const* d_in, const int* in_sizes, int n_in,
                              void* d_out, int out_size)
{
    const float* feature = (const float*)d_in[0];
    const float* xyz     = (const float*)d_in[1];
    const float* w1      = (const float*)d_in[2];
    const float* b1      = (const float*)d_in[3];
    const float* g1      = (const float*)d_in[4];
    const float* be1     = (const float*)d_in[5];
    const float* w2      = (const float*)d_in[6];
    const float* b2      = (const float*)d_in[7];
    const float* g2      = (const float*)d_in[8];
    const float* be2     = (const float*)d_in[9];
    const float* w3      = (const float*)d_in[10];
    const float* b3      = (const float*)d_in[11];
    float* out = (float*)d_out;

    float* y1 = nullptr; float* y2 = nullptr; float* ls = nullptr;
    cudaGetSymbolAddress((void**)&y1, g_y1);
    cudaGetSymbolAddress((void**)&y2, g_y2);
    cudaGetSymbolAddress((void**)&ls, g_ls);
    float* sc1; float* sh1; float* sc2; float* sh2;
    cudaGetSymbolAddress((void**)&sc1, g_sc1);
    cudaGetSymbolAddress((void**)&sh1, g_sh1);
    cudaGetSymbolAddress((void**)&sc2, g_sc2);
    cudaGetSymbolAddress((void**)&sh2, g_sh2);
    float* cx; float* cxT; float* cf; float* cfT;
    cudaGetSymbolAddress((void**)&cx,  g_costx);
    cudaGetSymbolAddress((void**)&cxT, g_costxT);
    cudaGetSymbolAddress((void**)&cf,  g_costf);
    cudaGetSymbolAddress((void**)&cfT, g_costfT);

    static int smem_set = 0;
    if (!smem_set) {
        cudaFuncSetAttribute(mma_gemm_kernel, cudaFuncAttributeMaxDynamicSharedMemorySize, (int)GEMM_SMEM);
        smem_set = 1;
    }

    init_kernel<<<(2*BB*NPTS + 255)/256, 256>>>();

    // layer 1: [512,1024] x [1024,4096]
    mma_gemm_kernel<<<dim3(NPTS/128, HH/128, BB), 256, GEMM_SMEM>>>(w1, feature, b1, y1, DD, HH);
    bn_stats_kernel<<<HH, 256>>>(y1, g1, be1, sc1, sh1);
    bn_relu_kernel<<<(BB*HH*NPTS/4 + 255)/256, 256>>>(y1, sc1, sh1);
    // layer 2: [512,512]
    mma_gemm_kernel<<<dim3(NPTS/128, HH/128, BB), 256, GEMM_SMEM>>>(w2, y1, b2, y2, HH, HH);
    bn_stats_kernel<<<HH, 256>>>(y2, g2, be2, sc2, sh2);
    bn_relu_kernel<<<(BB*HH*NPTS/4 + 255)/256, 256>>>(y2, sc2, sh2);
    // layer 3: [64,512] (M padded to 128 by row duplication inside)
    mma_gemm_kernel<<<dim3(NPTS/128, 1, BB), 256, GEMM_SMEM>>>(w3, y2, b3, ls, HH, KK);

    softmax_kernel<<<dim3(NPTS/256, BB), 256>>>();
    pi_kernel<<<dim3(KK, BB), 256>>>();
    mu_xyz_kernel<<<dim3(KK, BB), 256>>>(xyz);
    mufea_kernel<<<dim3(DD/64, BB), 256>>>(feature);
    invf_kernel<<<dim3(NPTS/256, BB), 256>>>(feature);
    invmu_kernel<<<BB, 64>>>();
    costf_kernel<<<dim3(NPTS/128, BB), 256>>>(feature);
    costx_kernel<<<dim3(NPTS/8, BB), 256>>>(xyz);
    transpose_kernel<<<dim3(NPTS/32, KK/32, BB), dim3(32, 8)>>>(cx, cxT);
    transpose_kernel<<<dim3(NPTS/32, KK/32, BB), dim3(32, 8)>>>(cf, cfT);

    for (int it = 0; it < 25; it++) {
        u_update_kernel<<<dim3(BB*NPTS/8, 2), 256>>>();
        v_update_kernel<<<dim3(BB*KK, 2), 256>>>();
    }

    reg_xyz_kernel<<<BB, 256>>>();
    reg_fea_kernel<<<BB, 256>>>();
    loss_kernel<<<dim3(BB*NPTS/8, 2), 256>>>();
    finalize_kernel<<<1, 32>>>(out, out_size);
}

// round 12
// speedup vs baseline: 1.8798x; 1.5340x over previous
#include <cuda_runtime.h>
#include <cuda_fp16.h>
#include <math.h>
#include <stdint.h>

#define BB   8
#define DD   1024
#define NPTS 4096
#define KK   64
#define HH   512

#define SEPS 1e-3f
#define INV_EPS (1.0f/1e-3f)

// ---------------- scratch (device globals; no allocation) ----------------
static __device__ float g_y1[BB*HH*NPTS];
static __device__ float g_y2[BB*HH*NPTS];
static __device__ float g_ls[BB*KK*NPTS];
static __device__ float g_score[BB*KK*NPTS];
static __device__ float g_lsn[BB*NPTS];
static __device__ float g_pi[BB*KK];
static __device__ float g_sc1[HH], g_sh1[HH], g_sc2[HH], g_sh2[HH];
static __device__ float g_muxyz[BB*3*KK];
static __device__ float g_mufea[BB*DD*KK];
static __device__ float g_invf[BB*NPTS];
static __device__ float g_invmu[BB*KK];
static __device__ float g_costx[BB*NPTS*KK];
static __device__ float g_costxT[BB*KK*NPTS];
static __device__ float g_costf[BB*NPTS*KK];
static __device__ float g_costfT[BB*KK*NPTS];
static __device__ float g_u[2*BB*NPTS];
static __device__ float g_v[2*BB*KK];
static __device__ float g_acc[4];

// ================= 3xFP16 GEMM via mma.sync m16n8k16 =================
// C[b][m][n] = sum_k W[m][k] * X[b][k][n] + bias[m]
// CTA tile 128Mx128N, BK=16, double buffered static smem (33KB), 2 CTA/SM.
// 8 warps: wm=wid>>2 (2), wn=wid&3 (4); warp tile 64x32 = 4mt x 4nt m16n8k16.
// Word = packed half2 (k even in low half).
// A layout (1024 words/tile): word(m,kp) at (m>>4)*128 + ((m&7)*4 + (kp&3))*4
//     + ((m>>3)&1) + ((kp>>2)<<1)   -> lane frag = uint4 at mtg*128 + lane*4
// B layout (8 x 136 padded): word(kp,n) at kp*136 + n
//     -> frag reg0 = [tg*136 + n], reg1 = [(tg+4)*136 + n], n = g + 8*ntg

__device__ __forceinline__ uint32_t split2h(float a, float b) {
    __half2 t = __halves2half2(__float2half_rn(a), __float2half_rn(b));
    return *reinterpret_cast<uint32_t*>(&t);
}
__device__ __forceinline__ uint32_t split2l(float a, float b) {
    __half ha = __float2half_rn(a), hb = __float2half_rn(b);
    float ra = a - __half2float(ha), rb = b - __half2float(hb);
    __half2 t = __halves2half2(__float2half_rn(ra), __float2half_rn(rb));
    return *reinterpret_cast<uint32_t*>(&t);
}

#define MMAH(d, a, b) \
    asm volatile("mma.sync.aligned.m16n8k16.row.col.f32.f16.f16.f32 " \
        "{%0,%1,%2,%3}, {%4,%5,%6,%7}, {%8,%9}, {%0,%1,%2,%3};" \
        : "+f"((d)[0]), "+f"((d)[1]), "+f"((d)[2]), "+f"((d)[3]) \
        : "r"((a).x), "r"((a).y), "r"((a).z), "r"((a).w), "r"((b).x), "r"((b).y))

#define BUFW 4224   // Ah[0,1024) Al[1024,2048) Bh[2048,3136) Bl[3136,4224)

__global__ __launch_bounds__(256, 2)
void mma_gemm_kernel(const float* __restrict__ W, const float* __restrict__ X,
                     const float* __restrict__ bias, float* __restrict__ C,
                     int Kd, int Mtot)
{
    __shared__ uint32_t sm[2 * BUFW];
    const int tid = threadIdx.x, wid = tid >> 5, lane = tid & 31;
    const int wm = wid >> 2, wn = wid & 3;
    const int g = lane >> 2, tg = lane & 3;
    const int b = blockIdx.z, n0 = blockIdx.x * 128, m0 = blockIdx.y * 128;
    const float* Xb = X + (size_t)b * Kd * NPTS;
    float* Cb = C + (size_t)b * Mtot * NPTS;

    float acc[4][4][4];
#pragma unroll
    for (int i = 0; i < 4; i++)
#pragma unroll
        for (int j = 0; j < 4; j++)
#pragma unroll
            for (int r = 0; r < 4; r++) acc[i][j][r] = 0.0f;

    const int CH = Kd / 16;

    // A task: tid -> mtg = tid>>5 (0..7), tt = tid&31; rows (mtg*16 + (tt>>2)) and +8,
    //   k pairs (2*tg', 2*tg'+1) and +8 where tg' = tt&3. Produces one lane-slot uint4.
    const int a_mtg = tid >> 5, a_tt = tid & 31;
    const int a_row = a_mtg * 16 + (a_tt >> 2);
    const int a_tg = a_tt & 3;
    // B task: kpg = tid>>5 (0..7), nq = tid&31; rows k=2kpg, 2kpg+1 at n quad.
    const int b_kpg = tid >> 5, b_nq = tid & 31;

    float2 a00, a01, a10, a11;
    float4 v0, v1;

    auto ldg_regs = [&](int k0) {
        int ms0 = m0 + a_row;     if (ms0 >= Mtot) ms0 -= Mtot;
        int ms1 = m0 + a_row + 8; if (ms1 >= Mtot) ms1 -= Mtot;
        const float* p0 = W + (size_t)ms0 * Kd + k0 + 2 * a_tg;
        const float* p1 = W + (size_t)ms1 * Kd + k0 + 2 * a_tg;
        a00 = *(const float2*)(p0);
        a01 = *(const float2*)(p0 + 8);
        a10 = *(const float2*)(p1);
        a11 = *(const float2*)(p1 + 8);
        const float* pb = Xb + (size_t)(k0 + 2 * b_kpg) * NPTS + n0 + b_nq * 4;
        v0 = *(const float4*)(pb);
        v1 = *(const float4*)(pb + (size_t)NPTS);
    };

    auto sts_smem = [&](int buf) {
        uint32_t* Ah = sm + buf * BUFW;
        uint32_t* Al = Ah + 1024;
        uint32_t* Bh = Ah + 2048;
        uint32_t* Bl = Ah + 3136;
        // A: one uint4 (4 fragment regs) for lane a_tt of tile a_mtg
        {
            uint4 hw, lw;
            hw.x = split2h(a00.x, a00.y); lw.x = split2l(a00.x, a00.y);  // row,   kp=tg
            hw.y = split2h(a10.x, a10.y); lw.y = split2l(a10.x, a10.y);  // row+8, kp=tg
            hw.z = split2h(a01.x, a01.y); lw.z = split2l(a01.x, a01.y);  // row,   kp=tg+4
            hw.w = split2h(a11.x, a11.y); lw.w = split2l(a11.x, a11.y);  // row+8, kp=tg+4
            int o = a_mtg * 128 + a_tt * 4;
            *(uint4*)(Ah + o) = hw;
            *(uint4*)(Al + o) = lw;
        }
        // B: 4 consecutive words at kpg*136 + nq*4
        {
            uint4 hw, lw;
            hw.x = split2h(v0.x, v1.x); lw.x = split2l(v0.x, v1.x);
            hw.y = split2h(v0.y, v1.y); lw.y = split2l(v0.y, v1.y);
            hw.z = split2h(v0.z, v1.z); lw.z = split2l(v0.z, v1.z);
            hw.w = split2h(v0.w, v1.w); lw.w = split2l(v0.w, v1.w);
            int o = b_kpg * 136 + b_nq * 4;
            *(uint4*)(Bh + o) = hw;
            *(uint4*)(Bl + o) = lw;
        }
    };

    ldg_regs(0);
    sts_smem(0);
    __syncthreads();

    for (int c = 0; c < CH; c++) {
        int p = c & 1;
        if (c + 1 < CH) ldg_regs((c + 1) * 16);

        const uint32_t* Ah = sm + p * BUFW;
        const uint32_t* Al = Ah + 1024;
        const uint32_t* Bh = Ah + 2048;
        const uint32_t* Bl = Ah + 3136;

        uint2 bh[4], bl[4];
#pragma unroll
        for (int nt = 0; nt < 4; nt++) {
            int n = g + (wn * 4 + nt) * 8;
            bh[nt].x = Bh[tg * 136 + n];
            bh[nt].y = Bh[(tg + 4) * 136 + n];
            bl[nt].x = Bl[tg * 136 + n];
            bl[nt].y = Bl[(tg + 4) * 136 + n];
        }
#pragma unroll
        for (int mt = 0; mt < 4; mt++) {
            int o = (wm * 4 + mt) * 128 + lane * 4;
            uint4 ah = *(const uint4*)(Ah + o);
            uint4 al = *(const uint4*)(Al + o);
#pragma unroll
            for (int nt = 0; nt < 4; nt++) {
                MMAH(acc[mt][nt], ah, bh[nt]);
                MMAH(acc[mt][nt], ah, bl[nt]);
                MMAH(acc[mt][nt], al, bh[nt]);
            }
        }

        if (c + 1 < CH) sts_smem(1 - p);
        __syncthreads();
    }

    // epilogue: direct stores + bias (C frag: rows g, g+8; cols 2tg, 2tg+1)
#pragma unroll
    for (int mt = 0; mt < 4; mt++) {
        int mrow = m0 + wm * 64 + mt * 16 + g;
#pragma unroll
        for (int half = 0; half < 2; half++) {
            int mg = mrow + half * 8;
            if (mg < Mtot) {
                float bi = bias[mg];
                float* crow = Cb + (size_t)mg * NPTS + n0 + wn * 32 + tg * 2;
#pragma unroll
                for (int nt = 0; nt < 4; nt++) {
                    float2 vv;
                    vv.x = acc[mt][nt][half * 2 + 0] + bi;
                    vv.y = acc[mt][nt][half * 2 + 1] + bi;
                    *(float2*)(crow + nt * 8) = vv;
                }
            }
        }
    }
}

// ================= remaining fp32 kernels =================
__global__ void init_kernel() {
    int i = blockIdx.x * blockDim.x + threadIdx.x;
    if (i < 2*BB*NPTS) g_u[i] = 0.0f;
    if (i < 2*BB*KK)   g_v[i] = 0.0f;
    if (i < 4)         g_acc[i] = 0.0f;
}

__global__ void bn_stats_kernel(const float* __restrict__ y,
                                const float* __restrict__ g, const float* __restrict__ be,
                                float* __restrict__ sc, float* __restrict__ sh)
{
    int h = blockIdx.x;
    int tid = threadIdx.x;
    float s = 0.0f, s2 = 0.0f;
    for (int b = 0; b < BB; b++) {
        const float* p = y + ((size_t)(b*HH + h)) * NPTS;
        for (int n = tid; n < NPTS; n += 256) { float v = p[n]; s += v; s2 += v*v; }
    }
    __shared__ float r1[256], r2[256];
    r1[tid] = s; r2[tid] = s2; __syncthreads();
    for (int o = 128; o > 0; o >>= 1) {
        if (tid < o) { r1[tid] += r1[tid+o]; r2[tid] += r2[tid+o]; }
        __syncthreads();
    }
    if (tid == 0) {
        float inv = 1.0f / (float)(BB*NPTS);
        float mean = r1[0] * inv;
        float var  = r2[0] * inv - mean*mean;
        float scale = g[h] / sqrtf(var + 1e-5f);
        sc[h] = scale;
        sh[h] = be[h] - mean * scale;
    }
}

__global__ void bn_relu_kernel(float* __restrict__ y,
                               const float* __restrict__ sc, const float* __restrict__ sh)
{
    size_t i4 = (size_t)blockIdx.x * blockDim.x + threadIdx.x;
    size_t total4 = (size_t)BB*HH*NPTS/4;
    if (i4 >= total4) return;
    int h = (int)((i4 / (NPTS/4)) % HH);
    float s = sc[h], t = sh[h];
    float4 v = ((float4*)y)[i4];
    v.x = fmaxf(0.0f, v.x*s + t);
    v.y = fmaxf(0.0f, v.y*s + t);
    v.z = fmaxf(0.0f, v.z*s + t);
    v.w = fmaxf(0.0f, v.w*s + t);
    ((float4*)y)[i4] = v;
}

__global__ void softmax_kernel() {
    int b = blockIdx.y;
    int n = blockIdx.x * 256 + threadIdx.x;
    const float* base = g_ls + (size_t)b*KK*NPTS + n;
    float mx = -1e30f;
#pragma unroll
    for (int k = 0; k < KK; k++) mx = fmaxf(mx, base[(size_t)k*NPTS]);
    float s = 0.0f;
#pragma unroll
    for (int k = 0; k < KK; k++) s += __expf(base[(size_t)k*NPTS] - mx);
    float inv = 1.0f / s;
    float* sb = g_score + (size_t)b*KK*NPTS + n;
#pragma unroll
    for (int k = 0; k < KK; k++) sb[(size_t)k*NPTS] = __expf(base[(size_t)k*NPTS] - mx) * inv;
    g_lsn[b*NPTS + n] = mx + logf(s);
}

__global__ void pi_kernel() {
    int k = blockIdx.x, b = blockIdx.y, tid = threadIdx.x;
    const float* p = g_score + (size_t)(b*KK + k) * NPTS;
    float s = 0.0f;
    for (int n = tid; n < NPTS; n += 256) s += p[n];
    __shared__ float r[256];
    r[tid] = s; __syncthreads();
    for (int o = 128; o > 0; o >>= 1) { if (tid < o) r[tid] += r[tid+o]; __syncthreads(); }
    if (tid == 0) g_pi[b*KK + k] = fmaxf(r[0], 1e-4f);
}

__global__ void mu_xyz_kernel(const float* __restrict__ xyz) {
    int k = blockIdx.x, b = blockIdx.y, tid = threadIdx.x;
    const float* sp = g_score + (size_t)(b*KK + k) * NPTS;
    const float* x0 = xyz + (size_t)(b*3 + 0) * NPTS;
    const float* x1 = xyz + (size_t)(b*3 + 1) * NPTS;
    const float* x2 = xyz + (size_t)(b*3 + 2) * NPTS;
    float a0 = 0, a1 = 0, a2 = 0;
    for (int n = tid; n < NPTS; n += 256) {
        float s = sp[n];
        a0 += s * x0[n]; a1 += s * x1[n]; a2 += s * x2[n];
    }
    __shared__ float r[256];
    float acc[3] = {a0, a1, a2};
    for (int d = 0; d < 3; d++) {
        r[tid] = acc[d]; __syncthreads();
        for (int o = 128; o > 0; o >>= 1) { if (tid < o) r[tid] += r[tid+o]; __syncthreads(); }
        if (tid == 0) {
            float invpi = 1.0f / g_pi[b*KK + k];
            g_muxyz[(b*3 + d)*KK + k] = r[0] * invpi;
        }
        __syncthreads();
    }
}

__global__ __launch_bounds__(256) void mufea_kernel(const float* __restrict__ feat) {
    int b = blockIdx.y;
    int d0 = blockIdx.x * 64;
    __shared__ float Fs[32][65];
    __shared__ float Ss[32][65];
    int tid = threadIdx.x;
    int tx = tid % 16, ty = tid / 16;
    float acc[4][4];
#pragma unroll
    for (int i = 0; i < 4; i++)
#pragma unroll
        for (int j = 0; j < 4; j++) acc[i][j] = 0.0f;

    for (int n0 = 0; n0 < NPTS; n0 += 32) {
#pragma unroll 8
        for (int i = tid; i < 64*32; i += 256) {
            int dd = i / 32, nn = i % 32;
            Fs[nn][dd] = feat[((size_t)b*DD + d0 + dd) * NPTS + n0 + nn];
        }
#pragma unroll 8
        for (int i = tid; i < 64*32; i += 256) {
            int kk = i / 32, nn = i % 32;
            Ss[nn][kk] = g_score[((size_t)b*KK + kk) * NPTS + n0 + nn];
        }
        __syncthreads();
#pragma unroll
        for (int nn = 0; nn < 32; nn++) {
            float a[4], s[4];
#pragma unroll
            for (int i = 0; i < 4; i++) a[i] = Fs[nn][ty*4 + i];
#pragma unroll
            for (int j = 0; j < 4; j++) s[j] = Ss[nn][tx*4 + j];
#pragma unroll
            for (int i = 0; i < 4; i++)
#pragma unroll
                for (int j = 0; j < 4; j++) acc[i][j] += a[i] * s[j];
        }
        __syncthreads();
    }
#pragma unroll
    for (int i = 0; i < 4; i++)
#pragma unroll
        for (int j = 0; j < 4; j++) {
            int k = tx*4 + j;
            g_mufea[((size_t)b*DD + d0 + ty*4 + i) * KK + k] = acc[i][j] / g_pi[b*KK + k];
        }
}

__global__ void invf_kernel(const float* __restrict__ feat) {
    int b = blockIdx.y;
    int n = blockIdx.x * 256 + threadIdx.x;
    float s = 0.0f;
    const float* p = feat + (size_t)b*DD*NPTS + n;
    for (int d = 0; d < DD; d++) { float v = p[(size_t)d*NPTS]; s += v*v; }
    g_invf[b*NPTS + n] = 1.0f / fmaxf(sqrtf(s), 1e-12f);
}

__global__ void invmu_kernel() {
    int b = blockIdx.x, k = threadIdx.x;
    float s = 0.0f;
    const float* p = g_mufea + (size_t)b*DD*KK + k;
    for (int d = 0; d < DD; d++) { float v = p[(size_t)d*KK]; s += v*v; }
    g_invmu[b*KK + k] = 1.0f / fmaxf(sqrtf(s), 1e-12f);
}

__global__ __launch_bounds__(256) void costf_kernel(const float* __restrict__ feat) {
    int b = blockIdx.y;
    int n0 = blockIdx.x * 128;
    __shared__ float As[16][128];
    __shared__ float Bs[16][64];
    int tid = threadIdx.x;
    int tn = tid % 16, tm = tid / 16;
    float acc[8][4];
#pragma unroll
    for (int i = 0; i < 8; i++)
#pragma unroll
        for (int j = 0; j < 4; j++) acc[i][j] = 0.0f;

    for (int d0 = 0; d0 < DD; d0 += 16) {
#pragma unroll 8
        for (int i = tid; i < 16*128; i += 256) {
            int dd = i / 128, nn = i % 128;
            As[dd][nn] = feat[((size_t)b*DD + d0 + dd) * NPTS + n0 + nn];
        }
#pragma unroll 4
        for (int i = tid; i < 16*64; i += 256) {
            int dd = i / 64, mm = i % 64;
            Bs[dd][mm] = g_mufea[((size_t)b*DD + d0 + dd) * KK + mm];
        }
        __syncthreads();
#pragma unroll
        for (int dd = 0; dd < 16; dd++) {
            float a[8], s[4];
#pragma unroll
            for (int i = 0; i < 8; i++) a[i] = As[dd][tn*8 + i];
#pragma unroll
            for (int j = 0; j < 4; j++) s[j] = Bs[dd][tm*4 + j];
#pragma unroll
            for (int i = 0; i < 8; i++)
#pragma unroll
                for (int j = 0; j < 4; j++) acc[i][j] += a[i] * s[j];
        }
        __syncthreads();
    }
#pragma unroll
    for (int i = 0; i < 8; i++) {
        int n = n0 + tn*8 + i;
        float fi = g_invf[b*NPTS + n];
#pragma unroll
        for (int j = 0; j < 4; j++) {
            int m = tm*4 + j;
            g_costf[((size_t)b*NPTS + n) * KK + m] =
                2.0f - 2.0f * acc[i][j] * fi * g_invmu[b*KK + m];
        }
    }
}

__global__ void costx_kernel(const float* __restrict__ xyz) {
    int b = blockIdx.y;
    __shared__ float smu[3][64];
    __shared__ float smun[64];
    int tid = threadIdx.x;
    if (tid < 192) smu[tid/64][tid%64] = g_muxyz[b*3*KK + tid];
    __syncthreads();
    if (tid < 64) smun[tid] = smu[0][tid]*smu[0][tid] + smu[1][tid]*smu[1][tid] + smu[2][tid]*smu[2][tid];
    __syncthreads();
    int w = tid >> 5, l = tid & 31;
    int n = blockIdx.x * 8 + w;
    float x0 = xyz[(size_t)(b*3 + 0)*NPTS + n];
    float x1 = xyz[(size_t)(b*3 + 1)*NPTS + n];
    float x2 = xyz[(size_t)(b*3 + 2)*NPTS + n];
    float xn = x0*x0 + x1*x1 + x2*x2;
    float* row = g_costx + ((size_t)b*NPTS + n) * KK;
#pragma unroll
    for (int t = 0; t < 2; t++) {
        int m = l + t*32;
        float d = x0*smu[0][m] + x1*smu[1][m] + x2*smu[2][m];
        row[m] = xn + smun[m] - 2.0f * d;
    }
}

__global__ void transpose_kernel(const float* __restrict__ src, float* __restrict__ dst) {
    __shared__ float t[32][33];
    int b = blockIdx.z;
    int n0 = blockIdx.x * 32, m0 = blockIdx.y * 32;
    int x = threadIdx.x, y = threadIdx.y;
    for (int j = y; j < 32; j += 8)
        t[j][x] = src[((size_t)b*NPTS + n0 + j) * KK + m0 + x];
    __syncthreads();
    for (int j = y; j < 32; j += 8)
        dst[((size_t)b*KK + m0 + j) * NPTS + n0 + x] = t[x][j];
}

__global__ void u_update_kernel() {
    int branch = blockIdx.y;
    const float* C = branch ? g_costf : g_costx;
    const float* v = (branch ? g_v + BB*KK : g_v);
    float* u = (branch ? g_u + BB*NPTS : g_u);
    int r0 = blockIdx.x * 8;
    int b = r0 >> 12;
    __shared__ float vs[64];
    if (threadIdx.x < 64) vs[threadIdx.x] = v[b*KK + threadIdx.x];
    __syncthreads();
    int w = threadIdx.x >> 5, l = threadIdx.x & 31;
    int r = r0 + w;
    const float* Crow = C + (size_t)r * KK;
    float a0 = (vs[l]      - Crow[l])      * INV_EPS;
    float a1 = (vs[l + 32] - Crow[l + 32]) * INV_EPS;
    float mx = fmaxf(a0, a1);
#pragma unroll
    for (int o = 16; o > 0; o >>= 1) mx = fmaxf(mx, __shfl_xor_sync(0xffffffffu, mx, o));
    float s = __expf(a0 - mx) + __expf(a1 - mx);
#pragma unroll
    for (int o = 16; o > 0; o >>= 1) s += __shfl_xor_sync(0xffffffffu, s, o);
    if (l == 0) {
        float epslogp = -SEPS * logf((float)NPTS);
        u[r] = epslogp - SEPS * (mx + logf(s));
    }
}

__global__ void v_update_kernel() {
    int branch = blockIdx.y;
    const float* CT = branch ? g_costfT : g_costxT;
    const float* u = (branch ? g_u + BB*NPTS : g_u);
    float* v = (branch ? g_v + BB*KK : g_v);
    int c = blockIdx.x;
    int b = c >> 6;
    const float* row = CT + (size_t)c * NPTS;
    const float* ub = u + b * NPTS;
    int tid = threadIdx.x;
    float vals[16];
    float mx = -1e30f;
#pragma unroll
    for (int i = 0; i < 16; i++) {
        int n = tid + i * 256;
        vals[i] = (ub[n] - row[n]) * INV_EPS;
        mx = fmaxf(mx, vals[i]);
    }
    __shared__ float r[256];
    r[tid] = mx; __syncthreads();
    for (int o = 128; o > 0; o >>= 1) { if (tid < o) r[tid] = fmaxf(r[tid], r[tid+o]); __syncthreads(); }
    mx = r[0]; __syncthreads();
    float s = 0.0f;
#pragma unroll
    for (int i = 0; i < 16; i++) s += __expf(vals[i] - mx);
    r[tid] = s; __syncthreads();
    for (int o = 128; o > 0; o >>= 1) { if (tid < o) r[tid] += r[tid+o]; __syncthreads(); }
    if (tid == 0) {
        float epslogq = -SEPS * logf((float)KK);
        v[c] = epslogq - SEPS * (mx + logf(r[0]));
    }
}

__global__ void reg_xyz_kernel() {
    int b = blockIdx.x, tid = threadIdx.x;
    float local = 0.0f;
    for (int e = tid; e < KK*KK; e += 256) {
        int m1 = e >> 6, m2 = e & 63;
        float s = 0.0f;
#pragma unroll
        for (int d = 0; d < 3; d++)
            s += g_muxyz[(b*3 + d)*KK + m1] * g_muxyz[(b*3 + d)*KK + m2];
        local += fabsf(s - (m1 == m2 ? 1.0f : 0.0f));
    }
    __shared__ float r[256];
    r[tid] = local; __syncthreads();
    for (int o = 128; o > 0; o >>= 1) { if (tid < o) r[tid] += r[tid+o]; __syncthreads(); }
    if (tid == 0) atomicAdd(&g_acc[2], r[0]);
}

__global__ void reg_fea_kernel() {
    int b = blockIdx.x, tid = threadIdx.x;
    float local = 0.0f;
    for (int e = tid; e < KK*KK; e += 256) {
        int m1 = e >> 6, m2 = e & 63;
        const float* p1 = g_mufea + (size_t)b*DD*KK + m1;
        const float* p2 = g_mufea + (size_t)b*DD*KK + m2;
        float s = 0.0f;
#pragma unroll 8
        for (int d = 0; d < DD; d++) s += p1[(size_t)d*KK] * p2[(size_t)d*KK];
        s *= g_invmu[b*KK + m1] * g_invmu[b*KK + m2];
        local += fabsf(s - (m1 == m2 ? 1.0f : 0.0f));
    }
    __shared__ float r[256];
    r[tid] = local; __syncthreads();
    for (int o = 128; o > 0; o >>= 1) { if (tid < o) r[tid] += r[tid+o]; __syncthreads(); }
    if (tid == 0) atomicAdd(&g_acc[3], r[0]);
}

__global__ void loss_kernel() {
    int branch = blockIdx.y;
    const float* C = branch ? g_costf : g_costx;
    const float* u = (branch ? g_u + BB*NPTS : g_u);
    const float* v = (branch ? g_v + BB*KK : g_v);
    int r0 = blockIdx.x * 8;
    int b = r0 >> 12;
    __shared__ float vs[64];
    if (threadIdx.x < 64) vs[threadIdx.x] = v[b*KK + threadIdx.x];
    __syncthreads();
    int w = threadIdx.x >> 5, l = threadIdx.x & 31;
    int r = r0 + w;
    int n = r & (NPTS - 1);
    const float* Crow = C + (size_t)r * KK;
    float ur = u[r];
    float lsnr = g_lsn[r];
    float acc = 0.0f;
#pragma unroll
    for (int t = 0; t < 2; t++) {
        int m = l + t*32;
        float gma = __expf((ur + vs[m] - Crow[m]) * INV_EPS);
        float lp = g_ls[((size_t)b*KK + m) * NPTS + n] - lsnr;
        acc += gma * lp;
    }
#pragma unroll
    for (int o = 16; o > 0; o >>= 1) acc += __shfl_xor_sync(0xffffffffu, acc, o);
    __shared__ float wsum[8];
    if (l == 0) wsum[w] = acc;
    __syncthreads();
    if (threadIdx.x == 0) {
        float t = 0.0f;
#pragma unroll
        for (int i = 0; i < 8; i++) t += wsum[i];
        atomicAdd(&g_acc[branch], t);
    }
}

__global__ void finalize_kernel(float* __restrict__ out, int out_size) {
    int i = threadIdx.x;
    for (int j = i; j < out_size; j += 32) out[j] = 0.0f;
    __syncwarp();
    if (i == 0) {
        float lx = g_acc[0], lf = g_acc[1], rx = g_acc[2], rf = g_acc[3];
        float loss_xyz = -lx / 8.0f;
        float loss_fea = -lf / 8.0f;
        float reg_fea  = 1e-4f * (rf / (float)(BB*KK*KK));
        float reg_xyz  = 0.001f * 1e-4f * (rx / (float)(BB*KK*KK));
        out[0] = loss_xyz + loss_fea + reg_fea + reg_xyz;
    }
}

// ---------------- launch ----------------
extern "C" void kernel_launch(void* const* d_in, const int* in_sizes, int n_in,
                              void* d_out, int out_size)
{
    const float* feature = (const float*)d_in[0];
    const float* xyz     = (const float*)d_in[1];
    const float* w1      = (const float*)d_in[2];
    const float* b1      = (const float*)d_in[3];
    const float* g1      = (const float*)d_in[4];
    const float* be1     = (const float*)d_in[5];
    const float* w2      = (const float*)d_in[6];
    const float* b2      = (const float*)d_in[7];
    const float* g2      = (const float*)d_in[8];
    const float* be2     = (const float*)d_in[9];
    const float* w3      = (const float*)d_in[10];
    const float* b3      = (const float*)d_in[11];
    float* out = (float*)d_out;

    float* y1 = nullptr; float* y2 = nullptr; float* ls = nullptr;
    cudaGetSymbolAddress((void**)&y1, g_y1);
    cudaGetSymbolAddress((void**)&y2, g_y2);
    cudaGetSymbolAddress((void**)&ls, g_ls);
    float* sc1; float* sh1; float* sc2; float* sh2;
    cudaGetSymbolAddress((void**)&sc1, g_sc1);
    cudaGetSymbolAddress((void**)&sh1, g_sh1);
    cudaGetSymbolAddress((void**)&sc2, g_sc2);
    cudaGetSymbolAddress((void**)&sh2, g_sh2);
    float* cx; float* cxT; float* cf; float* cfT;
    cudaGetSymbolAddress((void**)&cx,  g_costx);
    cudaGetSymbolAddress((void**)&cxT, g_costxT);
    cudaGetSymbolAddress((void**)&cf,  g_costf);
    cudaGetSymbolAddress((void**)&cfT, g_costfT);

    init_kernel<<<(2*BB*NPTS + 255)/256, 256>>>();

    // layer 1: [512,1024] x [1024,4096]
    mma_gemm_kernel<<<dim3(NPTS/128, HH/128, BB), 256>>>(w1, feature, b1, y1, DD, HH);
    bn_stats_kernel<<<HH, 256>>>(y1, g1, be1, sc1, sh1);
    bn_relu_kernel<<<(BB*HH*NPTS/4 + 255)/256, 256>>>(y1, sc1, sh1);
    // layer 2: [512,512]
    mma_gemm_kernel<<<dim3(NPTS/128, HH/128, BB), 256>>>(w2, y1, b2, y2, HH, HH);
    bn_stats_kernel<<<HH, 256>>>(y2, g2, be2, sc2, sh2);
    bn_relu_kernel<<<(BB*HH*NPTS/4 + 255)/256, 256>>>(y2, sc2, sh2);
    // layer 3: [64,512] (M padded to 128 by row duplication inside)
    mma_gemm_kernel<<<dim3(NPTS/128, 1, BB), 256>>>(w3, y2, b3, ls, HH, KK);

    softmax_kernel<<<dim3(NPTS/256, BB), 256>>>();
    pi_kernel<<<dim3(KK, BB), 256>>>();
    mu_xyz_kernel<<<dim3(KK, BB), 256>>>(xyz);
    mufea_kernel<<<dim3(DD/64, BB), 256>>>(feature);
    invf_kernel<<<dim3(NPTS/256, BB), 256>>>(feature);
    invmu_kernel<<<BB, 64>>>();
    costf_kernel<<<dim3(NPTS/128, BB), 256>>>(feature);
    costx_kernel<<<dim3(NPTS/8, BB), 256>>>(xyz);
    transpose_kernel<<<dim3(NPTS/32, KK/32, BB), dim3(32, 8)>>>(cx, cxT);
    transpose_kernel<<<dim3(NPTS/32, KK/32, BB), dim3(32, 8)>>>(cf, cfT);

    for (int it = 0; it < 25; it++) {
        u_update_kernel<<<dim3(BB*NPTS/8, 2), 256>>>();
        v_update_kernel<<<dim3(BB*KK, 2), 256>>>();
    }

    reg_xyz_kernel<<<BB, 256>>>();
    reg_fea_kernel<<<BB, 256>>>();
    loss_kernel<<<dim3(BB*NPTS/8, 2), 256>>>();
    finalize_kernel<<<1, 32>>>(out, out_size);
}

// round 13
// speedup vs baseline: 2.2029x; 1.1719x over previous
#include <cuda_runtime.h>
#include <cuda_fp16.h>
#include <math.h>
#include <stdint.h>

#define BB   8
#define DD   1024
#define NPTS 4096
#define KK   64
#define HH   512

#define SEPS 1e-3f
#define INV_EPS (1.0f/1e-3f)

// ---------------- scratch (device globals; no allocation) ----------------
static __device__ float g_y1[BB*HH*NPTS];
static __device__ float g_y2[BB*HH*NPTS];
static __device__ float g_ls[BB*KK*NPTS];
static __device__ float g_score[BB*KK*NPTS];
static __device__ float g_lsn[BB*NPTS];
static __device__ float g_pi[BB*KK];
static __device__ float g_sc1[HH], g_sh1[HH], g_sc2[HH], g_sh2[HH];
static __device__ float g_muxyz[BB*3*KK];
static __device__ float g_muT[BB*KK*DD];       // MuT[b][k][d]  (d contiguous)
static __device__ float g_invf[BB*NPTS];
static __device__ float g_invmu[BB*KK];
static __device__ float g_costx[BB*NPTS*KK];
static __device__ float g_costxT[BB*KK*NPTS];
static __device__ float g_costf[BB*NPTS*KK];
static __device__ float g_costfT[BB*KK*NPTS];
static __device__ float g_u[2*BB*NPTS];
static __device__ float g_v[2*BB*KK];
static __device__ float g_acc[4];

// ================= fp16x3 helpers =================
__device__ __forceinline__ uint32_t split2h(float a, float b) {
    __half2 t = __halves2half2(__float2half_rn(a), __float2half_rn(b));
    return *reinterpret_cast<uint32_t*>(&t);
}
__device__ __forceinline__ uint32_t split2l(float a, float b) {
    __half ha = __float2half_rn(a), hb = __float2half_rn(b);
    float ra = a - __half2float(ha), rb = b - __half2float(hb);
    __half2 t = __halves2half2(__float2half_rn(ra), __float2half_rn(rb));
    return *reinterpret_cast<uint32_t*>(&t);
}

#define MMAH(d, a, b) \
    asm volatile("mma.sync.aligned.m16n8k16.row.col.f32.f16.f16.f32 " \
        "{%0,%1,%2,%3}, {%4,%5,%6,%7}, {%8,%9}, {%0,%1,%2,%3};" \
        : "+f"((d)[0]), "+f"((d)[1]), "+f"((d)[2]), "+f"((d)[3]) \
        : "r"((a).x), "r"((a).y), "r"((a).z), "r"((a).w), "r"((b).x), "r"((b).y))

// ================= main 3xFP16 GEMM (TN): C[b][m][n] = sum_k W[m][k] X[b][k][n] =================
// mode 0: += bias[m]; mode 1: write 2 - 2*acc*invf[b,n]*invmu[b,m]  (cost-fea -> costfT)
#define BUFW 4224   // Ah[0,1024) Al[1024,2048) Bh[2048,3136) Bl[3136,4224)

__global__ __launch_bounds__(256, 2)
void mma_gemm_kernel(const float* __restrict__ W, const float* __restrict__ X,
                     const float* __restrict__ bias, float* __restrict__ C,
                     int Kd, int Mtot, int wstride, int mode,
                     const float* __restrict__ invf, const float* __restrict__ invmu)
{
    __shared__ uint32_t sm[2 * BUFW];
    const int tid = threadIdx.x, wid = tid >> 5, lane = tid & 31;
    const int wm = wid >> 2, wn = wid & 3;
    const int g = lane >> 2, tg = lane & 3;
    const int b = blockIdx.z, n0 = blockIdx.x * 128, m0 = blockIdx.y * 128;
    const float* Wb = W + (size_t)b * wstride;
    const float* Xb = X + (size_t)b * Kd * NPTS;
    float* Cb = C + (size_t)b * Mtot * NPTS;

    float acc[4][4][4];
#pragma unroll
    for (int i = 0; i < 4; i++)
#pragma unroll
        for (int j = 0; j < 4; j++)
#pragma unroll
            for (int r = 0; r < 4; r++) acc[i][j][r] = 0.0f;

    const int CH = Kd / 16;

    const int a_mtg = tid >> 5, a_tt = tid & 31;
    const int a_row = a_mtg * 16 + (a_tt >> 2);
    const int a_tg = a_tt & 3;
    const int b_kpg = tid >> 5, b_nq = tid & 31;

    float2 a00, a01, a10, a11;
    float4 v0, v1;

    auto ldg_regs = [&](int k0) {
        int ms0 = m0 + a_row;     if (ms0 >= Mtot) ms0 -= Mtot;
        int ms1 = m0 + a_row + 8; if (ms1 >= Mtot) ms1 -= Mtot;
        const float* p0 = Wb + (size_t)ms0 * Kd + k0 + 2 * a_tg;
        const float* p1 = Wb + (size_t)ms1 * Kd + k0 + 2 * a_tg;
        a00 = *(const float2*)(p0);
        a01 = *(const float2*)(p0 + 8);
        a10 = *(const float2*)(p1);
        a11 = *(const float2*)(p1 + 8);
        const float* pb = Xb + (size_t)(k0 + 2 * b_kpg) * NPTS + n0 + b_nq * 4;
        v0 = *(const float4*)(pb);
        v1 = *(const float4*)(pb + (size_t)NPTS);
    };

    auto sts_smem = [&](int buf) {
        uint32_t* Ah = sm + buf * BUFW;
        uint32_t* Al = Ah + 1024;
        uint32_t* Bh = Ah + 2048;
        uint32_t* Bl = Ah + 3136;
        {
            uint4 hw, lw;
            hw.x = split2h(a00.x, a00.y); lw.x = split2l(a00.x, a00.y);
            hw.y = split2h(a10.x, a10.y); lw.y = split2l(a10.x, a10.y);
            hw.z = split2h(a01.x, a01.y); lw.z = split2l(a01.x, a01.y);
            hw.w = split2h(a11.x, a11.y); lw.w = split2l(a11.x, a11.y);
            int o = a_mtg * 128 + a_tt * 4;
            *(uint4*)(Ah + o) = hw;
            *(uint4*)(Al + o) = lw;
        }
        {
            uint4 hw, lw;
            hw.x = split2h(v0.x, v1.x); lw.x = split2l(v0.x, v1.x);
            hw.y = split2h(v0.y, v1.y); lw.y = split2l(v0.y, v1.y);
            hw.z = split2h(v0.z, v1.z); lw.z = split2l(v0.z, v1.z);
            hw.w = split2h(v0.w, v1.w); lw.w = split2l(v0.w, v1.w);
            int o = b_kpg * 136 + b_nq * 4;
            *(uint4*)(Bh + o) = hw;
            *(uint4*)(Bl + o) = lw;
        }
    };

    ldg_regs(0);
    sts_smem(0);
    __syncthreads();

    for (int c = 0; c < CH; c++) {
        int p = c & 1;
        if (c + 1 < CH) ldg_regs((c + 1) * 16);

        const uint32_t* Ah = sm + p * BUFW;
        const uint32_t* Al = Ah + 1024;
        const uint32_t* Bh = Ah + 2048;
        const uint32_t* Bl = Ah + 3136;

        uint2 bh[4], bl[4];
#pragma unroll
        for (int nt = 0; nt < 4; nt++) {
            int n = g + (wn * 4 + nt) * 8;
            bh[nt].x = Bh[tg * 136 + n];
            bh[nt].y = Bh[(tg + 4) * 136 + n];
            bl[nt].x = Bl[tg * 136 + n];
            bl[nt].y = Bl[(tg + 4) * 136 + n];
        }
#pragma unroll
        for (int mt = 0; mt < 4; mt++) {
            int o = (wm * 4 + mt) * 128 + lane * 4;
            uint4 ah = *(const uint4*)(Ah + o);
            uint4 al = *(const uint4*)(Al + o);
#pragma unroll
            for (int nt = 0; nt < 4; nt++) {
                MMAH(acc[mt][nt], ah, bh[nt]);
                MMAH(acc[mt][nt], ah, bl[nt]);
                MMAH(acc[mt][nt], al, bh[nt]);
            }
        }

        if (c + 1 < CH) sts_smem(1 - p);
        __syncthreads();
    }

    // epilogue
#pragma unroll
    for (int mt = 0; mt < 4; mt++) {
        int mrow = m0 + wm * 64 + mt * 16 + g;
#pragma unroll
        for (int half = 0; half < 2; half++) {
            int mg = mrow + half * 8;
            if (mg < Mtot) {
                float* crow = Cb + (size_t)mg * NPTS + n0 + wn * 32 + tg * 2;
                if (mode == 0) {
                    float bi = bias[mg];
#pragma unroll
                    for (int nt = 0; nt < 4; nt++) {
                        float2 vv;
                        vv.x = acc[mt][nt][half * 2 + 0] + bi;
                        vv.y = acc[mt][nt][half * 2 + 1] + bi;
                        *(float2*)(crow + nt * 8) = vv;
                    }
                } else {
                    float im = invmu[b * KK + mg] * 2.0f;
                    const float* fr = invf + b * NPTS + n0 + wn * 32 + tg * 2;
#pragma unroll
                    for (int nt = 0; nt < 4; nt++) {
                        float2 f2 = *(const float2*)(fr + nt * 8);
                        float2 vv;
                        vv.x = 2.0f - acc[mt][nt][half * 2 + 0] * f2.x * im;
                        vv.y = 2.0f - acc[mt][nt][half * 2 + 1] * f2.y * im;
                        *(float2*)(crow + nt * 8) = vv;
                    }
                }
            }
        }
    }
}

// ================= NT fp16x3 GEMM: MuT[b][k][d] = (sum_n S[b][k][n] F[b][d][n]) / pi[b][k] ==========
// M=64 (k), N=128-tile over d, K=NPTS (contiguous in both operands). BK=16.
// Buffer: Ah[0,512) Al[512,1024) Bh[1024,2112) Bl[2112,3200). 8 warps: wn=wid, warp tile 64m x 16n.
#define NTBUFW 3200

__global__ __launch_bounds__(256, 2)
void mma_nt_kernel(const float* __restrict__ S, const float* __restrict__ F,
                   const float* __restrict__ pi, float* __restrict__ MuT)
{
    __shared__ uint32_t sm[2 * NTBUFW];
    const int tid = threadIdx.x, wid = tid >> 5, lane = tid & 31;
    const int g = lane >> 2, tg = lane & 3;
    const int b = blockIdx.z, n0 = blockIdx.x * 128;
    const float* Sb = S + (size_t)b * KK * NPTS;
    const float* Fb = F + (size_t)b * DD * NPTS;

    float acc[4][2][4];
#pragma unroll
    for (int i = 0; i < 4; i++)
#pragma unroll
        for (int j = 0; j < 2; j++)
#pragma unroll
            for (int r = 0; r < 4; r++) acc[i][j][r] = 0.0f;

    // staging tasks (3 per thread): A: m=tid>>2, kq=tid&3; B: n=tid>>2 (+64), kq=tid&3
    const int s_m = tid >> 2, s_kq = tid & 3;

    float4 a4, b40, b41;
    auto ldg_regs = [&](int k0) {
        a4  = *(const float4*)(Sb + (size_t)s_m * NPTS + k0 + s_kq * 4);
        b40 = *(const float4*)(Fb + (size_t)(n0 + s_m) * NPTS + k0 + s_kq * 4);
        b41 = *(const float4*)(Fb + (size_t)(n0 + s_m + 64) * NPTS + k0 + s_kq * 4);
    };

    auto sts_smem = [&](int buf) {
        uint32_t* Ah = sm + buf * NTBUFW;
        uint32_t* Al = Ah + 512;
        uint32_t* Bh = Ah + 1024;
        uint32_t* Bl = Ah + 2112;
        // A: word(m, kp) at mt*128 + ((m&7)*4 + (kp&3))*4 + ((m>>3)&1) + 2*(kp>>2)
        {
            int kp0 = 2 * s_kq;
            int mt = s_m >> 4;
            int base = mt * 128 + ((s_m & 7) * 4) * 4 + ((s_m >> 3) & 1);
            int o0 = base + (kp0 & 3) * 4 + 2 * (kp0 >> 2);
            int o1 = base + ((kp0 + 1) & 3) * 4 + 2 * ((kp0 + 1) >> 2);
            Ah[o0] = split2h(a4.x, a4.y);  Al[o0] = split2l(a4.x, a4.y);
            Ah[o1] = split2h(a4.z, a4.w);  Al[o1] = split2l(a4.z, a4.w);
        }
        // B: word(kp, n) at kp*136 + n
        {
            int kp0 = 2 * s_kq;
            int o0 = kp0 * 136 + s_m;
            int o1 = (kp0 + 1) * 136 + s_m;
            Bh[o0] = split2h(b40.x, b40.y);  Bl[o0] = split2l(b40.x, b40.y);
            Bh[o1] = split2h(b40.z, b40.w);  Bl[o1] = split2l(b40.z, b40.w);
            Bh[o0 + 64] = split2h(b41.x, b41.y);  Bl[o0 + 64] = split2l(b41.x, b41.y);
            Bh[o1 + 64] = split2h(b41.z, b41.w);  Bl[o1 + 64] = split2l(b41.z, b41.w);
        }
    };

    ldg_regs(0);
    sts_smem(0);
    __syncthreads();

    const int CH = NPTS / 16;
    for (int c = 0; c < CH; c++) {
        int p = c & 1;
        if (c + 1 < CH) ldg_regs((c + 1) * 16);

        const uint32_t* Ah = sm + p * NTBUFW;
        const uint32_t* Al = Ah + 512;
        const uint32_t* Bh = Ah + 1024;
        const uint32_t* Bl = Ah + 2112;

        uint2 bh[2], bl[2];
#pragma unroll
        for (int nt = 0; nt < 2; nt++) {
            int n = wid * 16 + nt * 8 + g;
            bh[nt].x = Bh[tg * 136 + n];
            bh[nt].y = Bh[(tg + 4) * 136 + n];
            bl[nt].x = Bl[tg * 136 + n];
            bl[nt].y = Bl[(tg + 4) * 136 + n];
        }
#pragma unroll
        for (int mt = 0; mt < 4; mt++) {
            int o = mt * 128 + lane * 4;
            uint4 ah = *(const uint4*)(Ah + o);
            uint4 al = *(const uint4*)(Al + o);
#pragma unroll
            for (int nt = 0; nt < 2; nt++) {
                MMAH(acc[mt][nt], ah, bh[nt]);
                MMAH(acc[mt][nt], ah, bl[nt]);
                MMAH(acc[mt][nt], al, bh[nt]);
            }
        }

        if (c + 1 < CH) sts_smem(1 - p);
        __syncthreads();
    }

    // epilogue: MuT[b][m][n_gl] = acc / pi[b][m]
#pragma unroll
    for (int mt = 0; mt < 4; mt++) {
#pragma unroll
        for (int half = 0; half < 2; half++) {
            int m = mt * 16 + g + half * 8;
            float ip = 1.0f / pi[b * KK + m];
            float* orow = MuT + ((size_t)b * KK + m) * DD + n0 + wid * 16 + tg * 2;
#pragma unroll
            for (int nt = 0; nt < 2; nt++) {
                float2 vv;
                vv.x = acc[mt][nt][half * 2 + 0] * ip;
                vv.y = acc[mt][nt][half * 2 + 1] * ip;
                *(float2*)(orow + nt * 8) = vv;
            }
        }
    }
}

// ================= remaining kernels =================
__global__ void init_kernel() {
    int i = blockIdx.x * blockDim.x + threadIdx.x;
    if (i < 2*BB*NPTS) g_u[i] = 0.0f;
    if (i < 2*BB*KK)   g_v[i] = 0.0f;
    if (i < 4)         g_acc[i] = 0.0f;
}

__global__ void bn_stats_kernel(const float* __restrict__ y,
                                const float* __restrict__ g, const float* __restrict__ be,
                                float* __restrict__ sc, float* __restrict__ sh)
{
    int h = blockIdx.x;
    int tid = threadIdx.x;
    float s = 0.0f, s2 = 0.0f;
    for (int b = 0; b < BB; b++) {
        const float* p = y + ((size_t)(b*HH + h)) * NPTS;
        for (int n = tid; n < NPTS; n += 256) { float v = p[n]; s += v; s2 += v*v; }
    }
    __shared__ float r1[256], r2[256];
    r1[tid] = s; r2[tid] = s2; __syncthreads();
    for (int o = 128; o > 0; o >>= 1) {
        if (tid < o) { r1[tid] += r1[tid+o]; r2[tid] += r2[tid+o]; }
        __syncthreads();
    }
    if (tid == 0) {
        float inv = 1.0f / (float)(BB*NPTS);
        float mean = r1[0] * inv;
        float var  = r2[0] * inv - mean*mean;
        float scale = g[h] / sqrtf(var + 1e-5f);
        sc[h] = scale;
        sh[h] = be[h] - mean * scale;
    }
}

__global__ void bn_relu_kernel(float* __restrict__ y,
                               const float* __restrict__ sc, const float* __restrict__ sh)
{
    size_t i4 = (size_t)blockIdx.x * blockDim.x + threadIdx.x;
    size_t total4 = (size_t)BB*HH*NPTS/4;
    if (i4 >= total4) return;
    int h = (int)((i4 / (NPTS/4)) % HH);
    float s = sc[h], t = sh[h];
    float4 v = ((float4*)y)[i4];
    v.x = fmaxf(0.0f, v.x*s + t);
    v.y = fmaxf(0.0f, v.y*s + t);
    v.z = fmaxf(0.0f, v.z*s + t);
    v.w = fmaxf(0.0f, v.w*s + t);
    ((float4*)y)[i4] = v;
}

__global__ void softmax_kernel() {
    int b = blockIdx.y;
    int n = blockIdx.x * 256 + threadIdx.x;
    const float* base = g_ls + (size_t)b*KK*NPTS + n;
    float mx = -1e30f;
#pragma unroll
    for (int k = 0; k < KK; k++) mx = fmaxf(mx, base[(size_t)k*NPTS]);
    float s = 0.0f;
#pragma unroll
    for (int k = 0; k < KK; k++) s += __expf(base[(size_t)k*NPTS] - mx);
    float inv = 1.0f / s;
    float* sb = g_score + (size_t)b*KK*NPTS + n;
#pragma unroll
    for (int k = 0; k < KK; k++) sb[(size_t)k*NPTS] = __expf(base[(size_t)k*NPTS] - mx) * inv;
    g_lsn[b*NPTS + n] = mx + logf(s);
}

__global__ void pi_kernel() {
    int k = blockIdx.x, b = blockIdx.y, tid = threadIdx.x;
    const float* p = g_score + (size_t)(b*KK + k) * NPTS;
    float s = 0.0f;
    for (int n = tid; n < NPTS; n += 256) s += p[n];
    __shared__ float r[256];
    r[tid] = s; __syncthreads();
    for (int o = 128; o > 0; o >>= 1) { if (tid < o) r[tid] += r[tid+o]; __syncthreads(); }
    if (tid == 0) g_pi[b*KK + k] = fmaxf(r[0], 1e-4f);
}

__global__ void mu_xyz_kernel(const float* __restrict__ xyz) {
    int k = blockIdx.x, b = blockIdx.y, tid = threadIdx.x;
    const float* sp = g_score + (size_t)(b*KK + k) * NPTS;
    const float* x0 = xyz + (size_t)(b*3 + 0) * NPTS;
    const float* x1 = xyz + (size_t)(b*3 + 1) * NPTS;
    const float* x2 = xyz + (size_t)(b*3 + 2) * NPTS;
    float a0 = 0, a1 = 0, a2 = 0;
    for (int n = tid; n < NPTS; n += 256) {
        float s = sp[n];
        a0 += s * x0[n]; a1 += s * x1[n]; a2 += s * x2[n];
    }
    __shared__ float r[256];
    float acc[3] = {a0, a1, a2};
    for (int d = 0; d < 3; d++) {
        r[tid] = acc[d]; __syncthreads();
        for (int o = 128; o > 0; o >>= 1) { if (tid < o) r[tid] += r[tid+o]; __syncthreads(); }
        if (tid == 0) {
            float invpi = 1.0f / g_pi[b*KK + k];
            g_muxyz[(b*3 + d)*KK + k] = r[0] * invpi;
        }
        __syncthreads();
    }
}

__global__ void invf_kernel(const float* __restrict__ feat) {
    int b = blockIdx.y;
    int n = blockIdx.x * 256 + threadIdx.x;
    float s = 0.0f;
    const float* p = feat + (size_t)b*DD*NPTS + n;
    for (int d = 0; d < DD; d++) { float v = p[(size_t)d*NPTS]; s += v*v; }
    g_invf[b*NPTS + n] = 1.0f / fmaxf(sqrtf(s), 1e-12f);
}

__global__ void invmu_kernel() {
    int b = blockIdx.x, k = threadIdx.x;
    const float4* p = (const float4*)(g_muT + ((size_t)b*KK + k) * DD);
    float s = 0.0f;
    for (int d4 = 0; d4 < DD/4; d4++) {
        float4 v = p[d4];
        s += v.x*v.x + v.y*v.y + v.z*v.z + v.w*v.w;
    }
    g_invmu[b*KK + k] = 1.0f / fmaxf(sqrtf(s), 1e-12f);
}

__global__ void costx_kernel(const float* __restrict__ xyz) {
    int b = blockIdx.y;
    __shared__ float smu[3][64];
    __shared__ float smun[64];
    int tid = threadIdx.x;
    if (tid < 192) smu[tid/64][tid%64] = g_muxyz[b*3*KK + tid];
    __syncthreads();
    if (tid < 64) smun[tid] = smu[0][tid]*smu[0][tid] + smu[1][tid]*smu[1][tid] + smu[2][tid]*smu[2][tid];
    __syncthreads();
    int w = tid >> 5, l = tid & 31;
    int n = blockIdx.x * 8 + w;
    float x0 = xyz[(size_t)(b*3 + 0)*NPTS + n];
    float x1 = xyz[(size_t)(b*3 + 1)*NPTS + n];
    float x2 = xyz[(size_t)(b*3 + 2)*NPTS + n];
    float xn = x0*x0 + x1*x1 + x2*x2;
    float* row = g_costx + ((size_t)b*NPTS + n) * KK;
#pragma unroll
    for (int t = 0; t < 2; t++) {
        int m = l + t*32;
        float d = x0*smu[0][m] + x1*smu[1][m] + x2*smu[2][m];
        row[m] = xn + smun[m] - 2.0f * d;
    }
}

// [b][n][m] -> [b][m][n]
__global__ void transpose_kernel(const float* __restrict__ src, float* __restrict__ dst) {
    __shared__ float t[32][33];
    int b = blockIdx.z;
    int n0 = blockIdx.x * 32, m0 = blockIdx.y * 32;
    int x = threadIdx.x, y = threadIdx.y;
    for (int j = y; j < 32; j += 8)
        t[j][x] = src[((size_t)b*NPTS + n0 + j) * KK + m0 + x];
    __syncthreads();
    for (int j = y; j < 32; j += 8)
        dst[((size_t)b*KK + m0 + j) * NPTS + n0 + x] = t[x][j];
}

// [b][m][n] -> [b][n][m]
__global__ void transposeT_kernel(const float* __restrict__ src, float* __restrict__ dst) {
    __shared__ float t[32][33];
    int b = blockIdx.z;
    int n0 = blockIdx.x * 32, m0 = blockIdx.y * 32;
    int x = threadIdx.x, y = threadIdx.y;
    for (int j = y; j < 32; j += 8)
        t[j][x] = src[((size_t)b*KK + m0 + j) * NPTS + n0 + x];
    __syncthreads();
    for (int j = y; j < 32; j += 8)
        dst[((size_t)b*NPTS + n0 + j) * KK + m0 + x] = t[x][j];
}

__global__ void u_update_kernel() {
    int branch = blockIdx.y;
    const float* C = branch ? g_costf : g_costx;
    const float* v = (branch ? g_v + BB*KK : g_v);
    float* u = (branch ? g_u + BB*NPTS : g_u);
    int r0 = blockIdx.x * 8;
    int b = r0 >> 12;
    __shared__ float vs[64];
    if (threadIdx.x < 64) vs[threadIdx.x] = v[b*KK + threadIdx.x];
    __syncthreads();
    int w = threadIdx.x >> 5, l = threadIdx.x & 31;
    int r = r0 + w;
    const float* Crow = C + (size_t)r * KK;
    float a0 = (vs[l]      - Crow[l])      * INV_EPS;
    float a1 = (vs[l + 32] - Crow[l + 32]) * INV_EPS;
    float mx = fmaxf(a0, a1);
#pragma unroll
    for (int o = 16; o > 0; o >>= 1) mx = fmaxf(mx, __shfl_xor_sync(0xffffffffu, mx, o));
    float s = __expf(a0 - mx) + __expf(a1 - mx);
#pragma unroll
    for (int o = 16; o > 0; o >>= 1) s += __shfl_xor_sync(0xffffffffu, s, o);
    if (l == 0) {
        float epslogp = -SEPS * logf((float)NPTS);
        u[r] = epslogp - SEPS * (mx + logf(s));
    }
}

__global__ void v_update_kernel() {
    int branch = blockIdx.y;
    const float* CT = branch ? g_costfT : g_costxT;
    const float* u = (branch ? g_u + BB*NPTS : g_u);
    float* v = (branch ? g_v + BB*KK : g_v);
    int c = blockIdx.x;
    int b = c >> 6;
    const float* row = CT + (size_t)c * NPTS;
    const float* ub = u + b * NPTS;
    int tid = threadIdx.x;
    float vals[16];
    float mx = -1e30f;
#pragma unroll
    for (int i = 0; i < 16; i++) {
        int n = tid + i * 256;
        vals[i] = (ub[n] - row[n]) * INV_EPS;
        mx = fmaxf(mx, vals[i]);
    }
    __shared__ float r[256];
    r[tid] = mx; __syncthreads();
    for (int o = 128; o > 0; o >>= 1) { if (tid < o) r[tid] = fmaxf(r[tid], r[tid+o]); __syncthreads(); }
    mx = r[0]; __syncthreads();
    float s = 0.0f;
#pragma unroll
    for (int i = 0; i < 16; i++) s += __expf(vals[i] - mx);
    r[tid] = s; __syncthreads();
    for (int o = 128; o > 0; o >>= 1) { if (tid < o) r[tid] += r[tid+o]; __syncthreads(); }
    if (tid == 0) {
        float epslogq = -SEPS * logf((float)KK);
        v[c] = epslogq - SEPS * (mx + logf(r[0]));
    }
}

__global__ void reg_xyz_kernel() {
    int b = blockIdx.x, tid = threadIdx.x;
    float local = 0.0f;
    for (int e = tid; e < KK*KK; e += 256) {
        int m1 = e >> 6, m2 = e & 63;
        float s = 0.0f;
#pragma unroll
        for (int d = 0; d < 3; d++)
            s += g_muxyz[(b*3 + d)*KK + m1] * g_muxyz[(b*3 + d)*KK + m2];
        local += fabsf(s - (m1 == m2 ? 1.0f : 0.0f));
    }
    __shared__ float r[256];
    r[tid] = local; __syncthreads();
    for (int o = 128; o > 0; o >>= 1) { if (tid < o) r[tid] += r[tid+o]; __syncthreads(); }
    if (tid == 0) atomicAdd(&g_acc[2], r[0]);
}

__global__ void reg_fea_kernel() {
    int b = blockIdx.x, tid = threadIdx.x;
    float local = 0.0f;
    for (int e = tid; e < KK*KK; e += 256) {
        int m1 = e >> 6, m2 = e & 63;
        const float4* p1 = (const float4*)(g_muT + ((size_t)b*KK + m1) * DD);
        const float4* p2 = (const float4*)(g_muT + ((size_t)b*KK + m2) * DD);
        float s = 0.0f;
#pragma unroll 4
        for (int d4 = 0; d4 < DD/4; d4++) {
            float4 v1 = p1[d4], v2 = p2[d4];
            s += v1.x*v2.x + v1.y*v2.y + v1.z*v2.z + v1.w*v2.w;
        }
        s *= g_invmu[b*KK + m1] * g_invmu[b*KK + m2];
        local += fabsf(s - (m1 == m2 ? 1.0f : 0.0f));
    }
    __shared__ float r[256];
    r[tid] = local; __syncthreads();
    for (int o = 128; o > 0; o >>= 1) { if (tid < o) r[tid] += r[tid+o]; __syncthreads(); }
    if (tid == 0) atomicAdd(&g_acc[3], r[0]);
}

__global__ void loss_kernel() {
    int branch = blockIdx.y;
    const float* C = branch ? g_costf : g_costx;
    const float* u = (branch ? g_u + BB*NPTS : g_u);
    const float* v = (branch ? g_v + BB*KK : g_v);
    int r0 = blockIdx.x * 8;
    int b = r0 >> 12;
    __shared__ float vs[64];
    if (threadIdx.x < 64) vs[threadIdx.x] = v[b*KK + threadIdx.x];
    __syncthreads();
    int w = threadIdx.x >> 5, l = threadIdx.x & 31;
    int r = r0 + w;
    int n = r & (NPTS - 1);
    const float* Crow = C + (size_t)r * KK;
    float ur = u[r];
    float lsnr = g_lsn[r];
    float acc = 0.0f;
#pragma unroll
    for (int t = 0; t < 2; t++) {
        int m = l + t*32;
        float gma = __expf((ur + vs[m] - Crow[m]) * INV_EPS);
        float lp = g_ls[((size_t)b*KK + m) * NPTS + n] - lsnr;
        acc += gma * lp;
    }
#pragma unroll
    for (int o = 16; o > 0; o >>= 1) acc += __shfl_xor_sync(0xffffffffu, acc, o);
    __shared__ float wsum[8];
    if (l == 0) wsum[w] = acc;
    __syncthreads();
    if (threadIdx.x == 0) {
        float t = 0.0f;
#pragma unroll
        for (int i = 0; i < 8; i++) t += wsum[i];
        atomicAdd(&g_acc[branch], t);
    }
}

__global__ void finalize_kernel(float* __restrict__ out, int out_size) {
    int i = threadIdx.x;
    for (int j = i; j < out_size; j += 32) out[j] = 0.0f;
    __syncwarp();
    if (i == 0) {
        float lx = g_acc[0], lf = g_acc[1], rx = g_acc[2], rf = g_acc[3];
        float loss_xyz = -lx / 8.0f;
        float loss_fea = -lf / 8.0f;
        float reg_fea  = 1e-4f * (rf / (float)(BB*KK*KK));
        float reg_xyz  = 0.001f * 1e-4f * (rx / (float)(BB*KK*KK));
        out[0] = loss_xyz + loss_fea + reg_fea + reg_xyz;
    }
}

// ---------------- launch ----------------
extern "C" void kernel_launch(void* const* d_in, const int* in_sizes, int n_in,
                              void* d_out, int out_size)
{
    const float* feature = (const float*)d_in[0];
    const float* xyz     = (const float*)d_in[1];
    const float* w1      = (const float*)d_in[2];
    const float* b1      = (const float*)d_in[3];
    const float* g1      = (const float*)d_in[4];
    const float* be1     = (const float*)d_in[5];
    const float* w2      = (const float*)d_in[6];
    const float* b2      = (const float*)d_in[7];
    const float* g2      = (const float*)d_in[8];
    const float* be2     = (const float*)d_in[9];
    const float* w3      = (const float*)d_in[10];
    const float* b3      = (const float*)d_in[11];
    float* out = (float*)d_out;

    float* y1; float* y2; float* ls;
    cudaGetSymbolAddress((void**)&y1, g_y1);
    cudaGetSymbolAddress((void**)&y2, g_y2);
    cudaGetSymbolAddress((void**)&ls, g_ls);
    float* sc1; float* sh1; float* sc2; float* sh2;
    cudaGetSymbolAddress((void**)&sc1, g_sc1);
    cudaGetSymbolAddress((void**)&sh1, g_sh1);
    cudaGetSymbolAddress((void**)&sc2, g_sc2);
    cudaGetSymbolAddress((void**)&sh2, g_sh2);
    float* cx; float* cxT; float* cf; float* cfT;
    cudaGetSymbolAddress((void**)&cx,  g_costx);
    cudaGetSymbolAddress((void**)&cxT, g_costxT);
    cudaGetSymbolAddress((void**)&cf,  g_costf);
    cudaGetSymbolAddress((void**)&cfT, g_costfT);
    float* scoreP; float* piP; float* muTP; float* invfP; float* invmuP;
    cudaGetSymbolAddress((void**)&scoreP, g_score);
    cudaGetSymbolAddress((void**)&piP,    g_pi);
    cudaGetSymbolAddress((void**)&muTP,   g_muT);
    cudaGetSymbolAddress((void**)&invfP,  g_invf);
    cudaGetSymbolAddress((void**)&invmuP, g_invmu);

    init_kernel<<<(2*BB*NPTS + 255)/256, 256>>>();

    // layer 1
    mma_gemm_kernel<<<dim3(NPTS/128, HH/128, BB), 256>>>(w1, feature, b1, y1, DD, HH, 0, 0, nullptr, nullptr);
    bn_stats_kernel<<<HH, 256>>>(y1, g1, be1, sc1, sh1);
    bn_relu_kernel<<<(BB*HH*NPTS/4 + 255)/256, 256>>>(y1, sc1, sh1);
    // layer 2
    mma_gemm_kernel<<<dim3(NPTS/128, HH/128, BB), 256>>>(w2, y1, b2, y2, HH, HH, 0, 0, nullptr, nullptr);
    bn_stats_kernel<<<HH, 256>>>(y2, g2, be2, sc2, sh2);
    bn_relu_kernel<<<(BB*HH*NPTS/4 + 255)/256, 256>>>(y2, sc2, sh2);
    // layer 3 (log_score)
    mma_gemm_kernel<<<dim3(NPTS/128, 1, BB), 256>>>(w3, y2, b3, ls, HH, KK, 0, 0, nullptr, nullptr);

    softmax_kernel<<<dim3(NPTS/256, BB), 256>>>();
    pi_kernel<<<dim3(KK, BB), 256>>>();
    mu_xyz_kernel<<<dim3(KK, BB), 256>>>(xyz);

    // MuT[b][k][d] via NT tensor-core GEMM
    mma_nt_kernel<<<dim3(DD/128, 1, BB), 256>>>(scoreP, feature, piP, muTP);
    invf_kernel<<<dim3(NPTS/256, BB), 256>>>(feature);
    invmu_kernel<<<BB, 64>>>();

    // costfT[b][m][n] via main GEMM (W = MuT per batch), then transpose -> costf
    mma_gemm_kernel<<<dim3(NPTS/128, 1, BB), 256>>>(muTP, feature, nullptr, cfT, DD, KK, KK*DD, 1, invfP, invmuP);
    transposeT_kernel<<<dim3(NPTS/32, KK/32, BB), dim3(32, 8)>>>(cfT, cf);

    costx_kernel<<<dim3(NPTS/8, BB), 256>>>(xyz);
    transpose_kernel<<<dim3(NPTS/32, KK/32, BB), dim3(32, 8)>>>(cx, cxT);

    for (int it = 0; it < 25; it++) {
        u_update_kernel<<<dim3(BB*NPTS/8, 2), 256>>>();
        v_update_kernel<<<dim3(BB*KK, 2), 256>>>();
    }

    reg_xyz_kernel<<<BB, 256>>>();
    reg_fea_kernel<<<BB, 256>>>();
    loss_kernel<<<dim3(BB*NPTS/8, 2), 256>>>();
    finalize_kernel<<<1, 32>>>(out, out_size);
}